// round 1
// baseline (speedup 1.0000x reference)
#include <cuda_runtime.h>
#include <math.h>
#include <stdint.h>

// Problem constants
#define Nn   8192
#define Ee   32768
#define DINc 1024
#define DHc  256
#define HHc  8
#define LLc  3
#define HDc  2048   // H*DH
#define NTc  5

// ---------------- device scratch (no cudaMalloc allowed) ----------------
__device__ float g_h[2 * Nn * DHc];              // ping-pong node features (16 MB)
__device__ float g_xl[(size_t)Nn * HDc];          // 64 MB
__device__ float g_xr[(size_t)Nn * HDc];          // 64 MB
__device__ float g_table[NTc * HDc];              // edge_emb @ We[l]
__device__ int   g_deg[Nn];
__device__ int   g_hist[Nn * NTc];
__device__ int   g_rowptr[Nn + 1];
__device__ int   g_woff[Nn];
__device__ int   g_eid[Ee];

// ---------------- CSR build ----------------
__global__ void k_zero() {
    int i = blockIdx.x * 256 + threadIdx.x;
    if (i < Nn) g_deg[i] = 0;
    if (i < Nn * NTc) g_hist[i] = 0;
}

__global__ void k_count(const int* __restrict__ ei, const int* __restrict__ ea) {
    int e = blockIdx.x * 256 + threadIdx.x;
    if (e < Ee) {
        int dst = ei[Ee + e];
        atomicAdd(&g_deg[dst], 1);
        atomicAdd(&g_hist[dst * NTc + ea[e]], 1);
    }
}

// single-block exclusive scan over 8192 degrees
__global__ void k_scan() {
    __shared__ int part[256];
    int tid = threadIdx.x;
    int base = tid * 32;
    int s = 0;
    for (int i = 0; i < 32; ++i) s += g_deg[base + i];
    part[tid] = s;
    __syncthreads();
    for (int off = 1; off < 256; off <<= 1) {
        int v = (tid >= off) ? part[tid - off] : 0;
        __syncthreads();
        part[tid] += v;
        __syncthreads();
    }
    int run = (tid == 0) ? 0 : part[tid - 1];
    for (int i = 0; i < 32; ++i) {
        int n = base + i;
        g_rowptr[n] = run;
        g_woff[n] = run;
        run += g_deg[n];
    }
    if (tid == 255) g_rowptr[Nn] = run;
}

__global__ void k_fill(const int* __restrict__ ei) {
    int e = blockIdx.x * 256 + threadIdx.x;
    if (e < Ee) {
        int dst = ei[Ee + e];
        int pos = atomicAdd(&g_woff[dst], 1);
        g_eid[pos] = e;
    }
}

// per-node insertion sort of edge ids -> deterministic accumulation order
__global__ void k_sort() {
    int n = blockIdx.x * 256 + threadIdx.x;
    if (n < Nn) {
        int r0 = g_rowptr[n], r1 = g_rowptr[n + 1];
        for (int i = r0 + 1; i < r1; ++i) {
            int v = g_eid[i];
            int j = i - 1;
            while (j >= r0 && g_eid[j] > v) { g_eid[j + 1] = g_eid[j]; --j; }
            g_eid[j + 1] = v;
        }
    }
}

// ---------------- edge-type table: table[t] = edge_emb[t] @ We[l] ----------------
__global__ void k_table(const float* __restrict__ edge_emb,
                        const float* __restrict__ We_l) {
    int idx = blockIdx.x * 256 + threadIdx.x;   // t*2048 + j
    if (idx < NTc * HDc) {
        int t = idx / HDc, j = idx % HDc;
        const float* w = We_l + j;
        const float* e = edge_emb + t * DHc;
        float s = 0.f;
        #pragma unroll 4
        for (int k = 0; k < DHc; ++k) s = fmaf(e[k], w[(size_t)k * HDc], s);
        g_table[idx] = s;
    }
}

// ---------------- generic fp32 tiled GEMM: C = A[MxK] @ B[KxN] + bias (+emb[types]) ----------------
// block tile 128x64, 256 threads, each computes 8x4
__global__ void __launch_bounds__(256)
k_gemm(const float* __restrict__ A, const float* __restrict__ B,
       const float* __restrict__ bias, float* __restrict__ C,
       int M, int K, int Nc,
       const float* __restrict__ emb, const int* __restrict__ types) {
    __shared__ float As[16][128];
    __shared__ float Bs[16][64];
    const int tid = threadIdx.x;
    const int brow = blockIdx.y * 128;
    const int bcol = blockIdx.x * 64;
    const int tr = (tid >> 4) << 3;   // 0..120 step 8
    const int tc = (tid & 15) << 2;   // 0..60 step 4
    float acc[8][4];
    #pragma unroll
    for (int i = 0; i < 8; ++i)
        #pragma unroll
        for (int j = 0; j < 4; ++j) acc[i][j] = 0.f;

    for (int k0 = 0; k0 < K; k0 += 16) {
        // load A tile 128x16 (512 float4s, 2 per thread), transposed into As[k][row]
        #pragma unroll
        for (int u = 0; u < 2; ++u) {
            int f = tid + u * 256;
            int ar = f >> 2;
            int kq = (f & 3) << 2;
            float4 v = *reinterpret_cast<const float4*>(
                &A[(size_t)(brow + ar) * K + k0 + kq]);
            As[kq + 0][ar] = v.x;
            As[kq + 1][ar] = v.y;
            As[kq + 2][ar] = v.z;
            As[kq + 3][ar] = v.w;
        }
        // load B tile 16x64 (256 float4s, 1 per thread)
        {
            int br = tid >> 4;
            int bc = (tid & 15) << 2;
            float4 v = *reinterpret_cast<const float4*>(
                &B[(size_t)(k0 + br) * Nc + bcol + bc]);
            *reinterpret_cast<float4*>(&Bs[br][bc]) = v;
        }
        __syncthreads();
        #pragma unroll
        for (int k = 0; k < 16; ++k) {
            float a[8], b[4];
            float4 a0 = *reinterpret_cast<const float4*>(&As[k][tr]);
            float4 a1 = *reinterpret_cast<const float4*>(&As[k][tr + 4]);
            a[0]=a0.x; a[1]=a0.y; a[2]=a0.z; a[3]=a0.w;
            a[4]=a1.x; a[5]=a1.y; a[6]=a1.z; a[7]=a1.w;
            float4 b0 = *reinterpret_cast<const float4*>(&Bs[k][tc]);
            b[0]=b0.x; b[1]=b0.y; b[2]=b0.z; b[3]=b0.w;
            #pragma unroll
            for (int i = 0; i < 8; ++i)
                #pragma unroll
                for (int j = 0; j < 4; ++j)
                    acc[i][j] = fmaf(a[i], b[j], acc[i][j]);
        }
        __syncthreads();
    }

    float b4[4];
    #pragma unroll
    for (int j = 0; j < 4; ++j) b4[j] = bias[bcol + tc + j];
    #pragma unroll
    for (int i = 0; i < 8; ++i) {
        int gm = brow + tr + i;
        float4 r;
        r.x = acc[i][0] + b4[0];
        r.y = acc[i][1] + b4[1];
        r.z = acc[i][2] + b4[2];
        r.w = acc[i][3] + b4[3];
        if (emb) {
            int ty = types[gm];
            const float* em = emb + (size_t)ty * Nc + bcol + tc;
            r.x += em[0]; r.y += em[1]; r.z += em[2]; r.w += em[3];
        }
        *reinterpret_cast<float4*>(&C[(size_t)gm * Nc + bcol + tc]) = r;
    }
}

// ---------------- fused GATv2 edge kernel (block per dst node, warp per head) ----------------
// online softmax: xl[src] read once per edge; logits never materialized.
__global__ void __launch_bounds__(256)
k_edge(const int* __restrict__ edge_index, const int* __restrict__ edge_attr,
       const float* __restrict__ att_l,   // [H*DH]
       const float* __restrict__ bgat_l,  // [DH]
       float* __restrict__ hout) {        // [N, DH]
    const int n = blockIdx.x;
    const int tid = threadIdx.x;
    const int lane = tid & 31;
    const int base = ((tid >> 5) << 8) + (lane << 3);   // head*256 + lane*8

    __shared__ float s_xr[HDc];
    __shared__ float s_att[HDc];
    __shared__ float s_lee[HDc];
    __shared__ float s_out[HDc];

    const int r0 = g_rowptr[n], r1 = g_rowptr[n + 1];
    const int deg = r1 - r0;
    const float inv = 1.0f / (float)(deg > 1 ? deg : 1);

    float c0 = (float)g_hist[n * NTc + 0];
    float c1 = (float)g_hist[n * NTc + 1];
    float c2 = (float)g_hist[n * NTc + 2];
    float c3 = (float)g_hist[n * NTc + 3];
    float c4 = (float)g_hist[n * NTc + 4];

    const float* xr_row = g_xr + (size_t)n * HDc;
    #pragma unroll
    for (int u = 0; u < 8; ++u) {
        int j = tid + u * 256;
        s_xr[j] = xr_row[j];
        s_att[j] = att_l[j];
        float v = c0 * g_table[0 * HDc + j];
        v = fmaf(c1, g_table[1 * HDc + j], v);
        v = fmaf(c2, g_table[2 * HDc + j], v);
        v = fmaf(c3, g_table[3 * HDc + j], v);
        v = fmaf(c4, g_table[4 * HDc + j], v);
        s_lee[j] = v * inv;
    }
    __syncthreads();

    float m = -1e30f, d = 0.f;
    float acc[8];
    #pragma unroll
    for (int i = 0; i < 8; ++i) acc[i] = 0.f;

    // real incoming edges, then the self-loop (idx == r1)
    for (int idx = r0; idx <= r1; ++idx) {
        int s, t = 0;
        bool isloop = (idx == r1);
        if (isloop) {
            s = n;
        } else {
            int eid = g_eid[idx];
            s = edge_index[eid];
            t = edge_attr[eid];
        }
        float xlv[8];
        const float4* xp = reinterpret_cast<const float4*>(g_xl + (size_t)s * HDc + base);
        float4 v0 = xp[0], v1 = xp[1];
        xlv[0]=v0.x; xlv[1]=v0.y; xlv[2]=v0.z; xlv[3]=v0.w;
        xlv[4]=v1.x; xlv[5]=v1.y; xlv[6]=v1.z; xlv[7]=v1.w;

        const float* tab = isloop ? (s_lee + base) : (g_table + (size_t)t * HDc + base);
        float part = 0.f;
        #pragma unroll
        for (int i = 0; i < 8; ++i) {
            float z = xlv[i] + s_xr[base + i] + tab[i];
            z = z > 0.f ? z : 0.2f * z;
            part = fmaf(z, s_att[base + i], part);
        }
        #pragma unroll
        for (int o = 16; o > 0; o >>= 1)
            part += __shfl_xor_sync(0xffffffffu, part, o);

        float mn = fmaxf(m, part);
        float sc = __expf(m - mn);
        float p  = __expf(part - mn);
        d = d * sc + p;
        #pragma unroll
        for (int i = 0; i < 8; ++i) acc[i] = fmaf(acc[i], sc, p * xlv[i]);
        m = mn;
    }

    float invd = 1.0f / d;
    #pragma unroll
    for (int i = 0; i < 8; ++i) s_out[base + i] = acc[i] * invd;
    __syncthreads();

    // head mean + bias + relu
    {
        int c = tid;  // 0..255
        float v = 0.f;
        #pragma unroll
        for (int h = 0; h < HHc; ++h) v += s_out[h * DHc + c];
        v = fmaf(v, 0.125f, bgat_l[c]);
        hout[(size_t)n * DHc + c] = fmaxf(v, 0.f);
    }
}

// ---------------- host orchestration ----------------
extern "C" void kernel_launch(void* const* d_in, const int* in_sizes, int n_in,
                              void* d_out, int out_size) {
    const float* x         = (const float*)d_in[0];
    const int*   edge_index= (const int*)  d_in[1];
    const int*   edge_attr = (const int*)  d_in[2];
    const int*   node_types= (const int*)  d_in[3];
    const float* W_in      = (const float*)d_in[4];
    const float* b_in      = (const float*)d_in[5];
    const float* node_emb  = (const float*)d_in[6];
    const float* edge_emb  = (const float*)d_in[7];
    const float* Wl        = (const float*)d_in[8];
    const float* bl        = (const float*)d_in[9];
    const float* Wr        = (const float*)d_in[10];
    const float* br        = (const float*)d_in[11];
    const float* We        = (const float*)d_in[12];
    const float* att       = (const float*)d_in[13];
    const float* b_gat     = (const float*)d_in[14];
    const float* W_out     = (const float*)d_in[15];
    const float* b_out     = (const float*)d_in[16];
    float* out = (float*)d_out;

    float* h_base;  cudaGetSymbolAddress((void**)&h_base, g_h);
    float* xl;      cudaGetSymbolAddress((void**)&xl, g_xl);
    float* xr;      cudaGetSymbolAddress((void**)&xr, g_xr);

    // CSR + histogram (edge structure is layer-invariant)
    k_zero<<<(Nn * NTc + 255) / 256, 256>>>();
    k_count<<<(Ee + 255) / 256, 256>>>(edge_index, edge_attr);
    k_scan<<<1, 256>>>();
    k_fill<<<(Ee + 255) / 256, 256>>>(edge_index);
    k_sort<<<(Nn + 255) / 256, 256>>>();

    // input projection: h0 = x @ W_in + b_in + node_emb[node_types]
    {
        dim3 grid(DHc / 64, Nn / 128);
        k_gemm<<<grid, 256>>>(x, W_in, b_in, h_base, Nn, DINc, DHc,
                              node_emb, node_types);
    }

    int sel = 0;
    for (int l = 0; l < LLc; ++l) {
        const float* h_cur = h_base + (size_t)sel * Nn * DHc;
        float* h_nxt = h_base + (size_t)(sel ^ 1) * Nn * DHc;

        k_table<<<(NTc * HDc + 255) / 256, 256>>>(edge_emb,
                                                  We + (size_t)l * DHc * HDc);
        dim3 grid(HDc / 64, Nn / 128);
        k_gemm<<<grid, 256>>>(h_cur, Wl + (size_t)l * DHc * HDc,
                              bl + (size_t)l * HDc, xl, Nn, DHc, HDc,
                              nullptr, nullptr);
        k_gemm<<<grid, 256>>>(h_cur, Wr + (size_t)l * DHc * HDc,
                              br + (size_t)l * HDc, xr, Nn, DHc, HDc,
                              nullptr, nullptr);
        k_edge<<<Nn, 256>>>(edge_index, edge_attr,
                            att + (size_t)l * HHc * DHc,
                            b_gat + (size_t)l * DHc,
                            h_nxt);
        sel ^= 1;
    }

    // output projection
    {
        const float* h_cur = h_base + (size_t)sel * Nn * DHc;
        dim3 grid(DHc / 64, Nn / 128);
        k_gemm<<<grid, 256>>>(h_cur, W_out, b_out, out, Nn, DHc, DHc,
                              nullptr, nullptr);
    }
    (void)in_sizes; (void)n_in; (void)out_size;
}

// round 3
// speedup vs baseline: 1.6366x; 1.6366x over previous
#include <cuda_runtime.h>
#include <cuda_bf16.h>
#include <math.h>
#include <stdint.h>

// Problem constants
#define Nn   8192
#define Ee   32768
#define DINc 1024
#define DHc  256
#define HHc  8
#define LLc  3
#define HDc  2048   // H*DH
#define NTc  5

// ---------------- device scratch (no cudaMalloc allowed) ----------------
__device__ float g_h[2 * Nn * DHc];               // ping-pong node features
__device__ float g_xl[(size_t)Nn * HDc];
__device__ float g_xr[(size_t)Nn * HDc];
__device__ float g_table[NTc * HDc];
__device__ int   g_deg[Nn];
__device__ int   g_hist[Nn * NTc];
__device__ int   g_rowptr[Nn + 1];
__device__ int   g_woff[Nn];
__device__ int   g_eid[Ee];

// bf16x3 packed operands
__device__ __nv_bfloat16 g_Apack[(size_t)Nn * 3 * DINc];
__device__ __nv_bfloat16 g_Bpack[10420224];

#define OFF_WIN  0
#define SZ_WIN   (DHc * 3 * DINc)
#define SZ_WLR   (HDc * 3 * DHc)
#define OFF_WL(l) (SZ_WIN + (size_t)(l) * SZ_WLR)
#define OFF_WR(l) (SZ_WIN + (size_t)(3 + (l)) * SZ_WLR)
#define OFF_WOUT (SZ_WIN + (size_t)6 * SZ_WLR)

// ---------------- PTX helpers ----------------
__device__ __forceinline__ uint32_t smem_u32(const void* p) {
    uint32_t a;
    asm("{ .reg .u64 t; cvta.to.shared.u64 t, %1; cvt.u32.u64 %0, t; }" : "=r"(a) : "l"(p));
    return a;
}
__device__ __forceinline__ void cp16(uint32_t d, const void* g) {
    asm volatile("cp.async.cg.shared.global [%0], [%1], 16;" :: "r"(d), "l"(g));
}
__device__ __forceinline__ void ldsm_x4(uint32_t* r, uint32_t addr) {
    asm volatile("ldmatrix.sync.aligned.m8n8.x4.shared.b16 {%0,%1,%2,%3}, [%4];"
                 : "=r"(r[0]), "=r"(r[1]), "=r"(r[2]), "=r"(r[3]) : "r"(addr));
}
__device__ __forceinline__ void mma_bf16(float* c, const uint32_t* a, uint32_t b0, uint32_t b1) {
    asm volatile(
        "mma.sync.aligned.m16n8k16.row.col.f32.bf16.bf16.f32 "
        "{%0,%1,%2,%3}, {%4,%5,%6,%7}, {%8,%9}, {%0,%1,%2,%3};"
        : "+f"(c[0]), "+f"(c[1]), "+f"(c[2]), "+f"(c[3])
        : "r"(a[0]), "r"(a[1]), "r"(a[2]), "r"(a[3]), "r"(b0), "r"(b1));
}

// ---------------- CSR build ----------------
__global__ void k_zero() {
    int i = blockIdx.x * 256 + threadIdx.x;
    if (i < Nn) g_deg[i] = 0;
    if (i < Nn * NTc) g_hist[i] = 0;
}
__global__ void k_count(const int* __restrict__ ei, const int* __restrict__ ea) {
    int e = blockIdx.x * 256 + threadIdx.x;
    if (e < Ee) {
        int dst = ei[Ee + e];
        atomicAdd(&g_deg[dst], 1);
        atomicAdd(&g_hist[dst * NTc + ea[e]], 1);
    }
}
__global__ void k_scan() {
    __shared__ int part[256];
    int tid = threadIdx.x;
    int base = tid * 32;
    int s = 0;
    for (int i = 0; i < 32; ++i) s += g_deg[base + i];
    part[tid] = s;
    __syncthreads();
    for (int off = 1; off < 256; off <<= 1) {
        int v = (tid >= off) ? part[tid - off] : 0;
        __syncthreads();
        part[tid] += v;
        __syncthreads();
    }
    int run = (tid == 0) ? 0 : part[tid - 1];
    for (int i = 0; i < 32; ++i) {
        int n = base + i;
        g_rowptr[n] = run;
        g_woff[n] = run;
        run += g_deg[n];
    }
    if (tid == 255) g_rowptr[Nn] = run;
}
__global__ void k_fill(const int* __restrict__ ei) {
    int e = blockIdx.x * 256 + threadIdx.x;
    if (e < Ee) {
        int dst = ei[Ee + e];
        int pos = atomicAdd(&g_woff[dst], 1);
        g_eid[pos] = e;
    }
}
__global__ void k_sort() {
    int n = blockIdx.x * 256 + threadIdx.x;
    if (n < Nn) {
        int r0 = g_rowptr[n], r1 = g_rowptr[n + 1];
        for (int i = r0 + 1; i < r1; ++i) {
            int v = g_eid[i];
            int j = i - 1;
            while (j >= r0 && g_eid[j] > v) { g_eid[j + 1] = g_eid[j]; --j; }
            g_eid[j + 1] = v;
        }
    }
}

// ---------------- edge-type table ----------------
__global__ void k_table(const float* __restrict__ edge_emb,
                        const float* __restrict__ We_l) {
    int idx = blockIdx.x * 256 + threadIdx.x;
    if (idx < NTc * HDc) {
        int t = idx / HDc, j = idx % HDc;
        const float* w = We_l + j;
        const float* e = edge_emb + t * DHc;
        float s = 0.f;
        #pragma unroll 4
        for (int k = 0; k < DHc; ++k) s = fmaf(e[k], w[(size_t)k * HDc], s);
        g_table[idx] = s;
    }
}

// ---------------- packing kernels (bf16 hi/lo split) ----------------
__global__ void k_pack_a(const float* __restrict__ A, __nv_bfloat16* __restrict__ P, int K) {
    int idx = blockIdx.x * 256 + threadIdx.x;
    int m = idx / K, k = idx - m * K;
    float v = A[idx];
    __nv_bfloat16 hi = __float2bfloat16(v);
    __nv_bfloat16 lo = __float2bfloat16(v - __bfloat162float(hi));
    size_t b = (size_t)m * 3 * K;
    P[b + k]         = hi;
    P[b + K + k]     = lo;
    P[b + 2 * K + k] = hi;
}
__global__ void k_pack_w(const float* __restrict__ W, __nv_bfloat16* __restrict__ P,
                         int K, int N) {
    __shared__ float t[32][33];
    int nb = blockIdx.x, kb = blockIdx.y;
    int tx = threadIdx.x & 31;
    int ty = threadIdx.x >> 5;
    #pragma unroll
    for (int i = 0; i < 32; i += 8)
        t[ty + i][tx] = W[(size_t)(kb * 32 + ty + i) * N + nb * 32 + tx];
    __syncthreads();
    int K3 = 3 * K;
    #pragma unroll
    for (int i = 0; i < 32; i += 8) {
        int n = nb * 32 + ty + i;
        int k = kb * 32 + tx;
        float v = t[tx][ty + i];
        __nv_bfloat16 hi = __float2bfloat16(v);
        __nv_bfloat16 lo = __float2bfloat16(v - __bfloat162float(hi));
        P[(size_t)n * K3 + k]         = hi;
        P[(size_t)n * K3 + K + k]     = hi;
        P[(size_t)n * K3 + 2 * K + k] = lo;
    }
}

// ---------------- mma.sync bf16 GEMM: C[M,Nc] = A[M,Ktot] @ B[Nc,Ktot]^T + bias ----------------
// CTA 128x128, 8 warps (warp tile 32x64), BK=64 bf16 (128B SW128 rows), 4-stage cp.async.
#define GSTAGE 4
#define STG_BYTES 32768
#define GEMM_SMEM (GSTAGE * STG_BYTES)

__global__ void __launch_bounds__(256, 1)
k_gemm_mma(const __nv_bfloat16* __restrict__ A, const __nv_bfloat16* __restrict__ B,
           const float* __restrict__ bias, float* __restrict__ C,
           int Ktot, int Nc, const float* __restrict__ emb, const int* __restrict__ types) {
    extern __shared__ __align__(1024) char smem[];
    const uint32_t sb = smem_u32(smem);
    const int tid = threadIdx.x;
    const int lane = tid & 31, w = tid >> 5;
    const int wm = w & 3, wn = w >> 2;
    const int row0 = blockIdx.y * 128;
    const int col0 = blockIdx.x * 128;
    const int nch = Ktot >> 6;

    float acc[2][8][4];
    #pragma unroll
    for (int i = 0; i < 2; ++i)
        #pragma unroll
        for (int j = 0; j < 8; ++j)
            #pragma unroll
            for (int q = 0; q < 4; ++q) acc[i][j][q] = 0.f;

    // per-thread cp.async constants: 8 chunks of 16B (4 for A, 4 for B)
    uint32_t sm_off[4];
    const __nv_bfloat16* gA[4];
    const __nv_bfloat16* gB[4];
    #pragma unroll
    for (int u = 0; u < 4; ++u) {
        int i = tid + u * 256;
        int r = i >> 3, seg = i & 7;
        uint32_t off = (uint32_t)(r * 128 + seg * 16);
        sm_off[u] = off ^ ((off >> 3) & 0x70);
        gA[u] = A + (size_t)(row0 + r) * Ktot + (seg << 3);
        gB[u] = B + (size_t)(col0 + r) * Ktot + (seg << 3);
    }
    auto load_chunk = [&](int c) {
        const uint32_t s = sb + (uint32_t)((c & (GSTAGE - 1)) * STG_BYTES);
        const int kof = c << 6;
        #pragma unroll
        for (int u = 0; u < 4; ++u) cp16(s + sm_off[u], gA[u] + kof);
        #pragma unroll
        for (int u = 0; u < 4; ++u) cp16(s + 16384 + sm_off[u], gB[u] + kof);
        asm volatile("cp.async.commit_group;");
    };

    #pragma unroll
    for (int c = 0; c < GSTAGE; ++c) load_chunk(c);

    // hoisted ldmatrix address components (swizzle XOR = (row&7)<<4, row-only)
    uint32_t a_base[2], a_swz[2];
    #pragma unroll
    for (int mb = 0; mb < 2; ++mb) {
        int row = wm * 32 + mb * 16 + (lane & 15);
        a_base[mb] = (uint32_t)(row * 128 + ((lane >> 4) << 4));
        a_swz[mb] = (uint32_t)((row & 7) << 4);
    }
    uint32_t b_base[4], b_swz[4];
    #pragma unroll
    for (int nb = 0; nb < 4; ++nb) {
        int row = wn * 64 + nb * 16 + (lane & 7) + ((lane >> 4) << 3);
        b_base[nb] = (uint32_t)(row * 128 + (((lane >> 3) & 1) << 4));
        b_swz[nb] = (uint32_t)((row & 7) << 4);
    }

    for (int c = 0; c < nch; ++c) {
        asm volatile("cp.async.wait_group %0;" :: "n"(GSTAGE - 1));
        __syncthreads();
        const uint32_t stb = sb + (uint32_t)((c & (GSTAGE - 1)) * STG_BYTES);
        #pragma unroll
        for (int kk = 0; kk < 4; ++kk) {
            const uint32_t kby = (uint32_t)(kk * 32);
            uint32_t a[2][4];
            #pragma unroll
            for (int mb = 0; mb < 2; ++mb) {
                uint32_t addr = stb + ((a_base[mb] + kby) ^ a_swz[mb]);
                ldsm_x4(a[mb], addr);
            }
            uint32_t b[4][4];
            #pragma unroll
            for (int nb = 0; nb < 4; ++nb) {
                uint32_t addr = stb + 16384 + ((b_base[nb] + kby) ^ b_swz[nb]);
                ldsm_x4(b[nb], addr);
            }
            #pragma unroll
            for (int mb = 0; mb < 2; ++mb)
                #pragma unroll
                for (int nb = 0; nb < 4; ++nb) {
                    mma_bf16(acc[mb][2 * nb],     a[mb], b[nb][0], b[nb][1]);
                    mma_bf16(acc[mb][2 * nb + 1], a[mb], b[nb][2], b[nb][3]);
                }
        }
        __syncthreads();
        if (c + GSTAGE < nch) load_chunk(c + GSTAGE);
        else asm volatile("cp.async.commit_group;");
    }

    // epilogue: direct register -> global, float2 stores, fused bias/emb
    const int r_base = row0 + wm * 32 + (lane >> 2);
    const int c_base = col0 + wn * 64 + ((lane & 3) << 1);
    #pragma unroll
    for (int mb = 0; mb < 2; ++mb) {
        const int r1 = r_base + mb * 16;
        const int r2 = r1 + 8;
        float e1x = 0.f, e1y = 0.f, e2x = 0.f, e2y = 0.f;
        #pragma unroll
        for (int nt = 0; nt < 8; ++nt) {
            const int col = c_base + nt * 8;
            float bx = bias[col], by = bias[col + 1];
            if (emb) {
                const float* em1 = emb + (size_t)types[r1] * Nc + col;
                const float* em2 = emb + (size_t)types[r2] * Nc + col;
                e1x = em1[0]; e1y = em1[1]; e2x = em2[0]; e2y = em2[1];
            }
            float2 v0, v1;
            v0.x = acc[mb][nt][0] + bx + e1x;
            v0.y = acc[mb][nt][1] + by + e1y;
            v1.x = acc[mb][nt][2] + bx + e2x;
            v1.y = acc[mb][nt][3] + by + e2y;
            *reinterpret_cast<float2*>(&C[(size_t)r1 * Nc + col]) = v0;
            *reinterpret_cast<float2*>(&C[(size_t)r2 * Nc + col]) = v1;
        }
    }
}

// ---------------- fused GATv2 edge kernel (known-good) ----------------
__global__ void __launch_bounds__(256)
k_edge(const int* __restrict__ edge_index, const int* __restrict__ edge_attr,
       const float* __restrict__ att_l, const float* __restrict__ bgat_l,
       float* __restrict__ hout) {
    const int n = blockIdx.x;
    const int tid = threadIdx.x;
    const int lane = tid & 31;
    const int base = ((tid >> 5) << 8) + (lane << 3);

    __shared__ float s_xr[HDc];
    __shared__ float s_att[HDc];
    __shared__ float s_lee[HDc];
    __shared__ float s_out[HDc];

    const int r0 = g_rowptr[n], r1 = g_rowptr[n + 1];
    const int deg = r1 - r0;
    const float inv = 1.0f / (float)(deg > 1 ? deg : 1);

    float c0 = (float)g_hist[n * NTc + 0];
    float c1 = (float)g_hist[n * NTc + 1];
    float c2 = (float)g_hist[n * NTc + 2];
    float c3 = (float)g_hist[n * NTc + 3];
    float c4 = (float)g_hist[n * NTc + 4];

    const float* xr_row = g_xr + (size_t)n * HDc;
    #pragma unroll
    for (int u = 0; u < 8; ++u) {
        int j = tid + u * 256;
        s_xr[j] = xr_row[j];
        s_att[j] = att_l[j];
        float v = c0 * g_table[0 * HDc + j];
        v = fmaf(c1, g_table[1 * HDc + j], v);
        v = fmaf(c2, g_table[2 * HDc + j], v);
        v = fmaf(c3, g_table[3 * HDc + j], v);
        v = fmaf(c4, g_table[4 * HDc + j], v);
        s_lee[j] = v * inv;
    }
    __syncthreads();

    float m = -1e30f, d = 0.f;
    float acc[8];
    #pragma unroll
    for (int i = 0; i < 8; ++i) acc[i] = 0.f;

    for (int idx = r0; idx <= r1; ++idx) {
        int s, t = 0;
        bool isloop = (idx == r1);
        if (isloop) {
            s = n;
        } else {
            int eid = g_eid[idx];
            s = edge_index[eid];
            t = edge_attr[eid];
        }
        float xlv[8];
        const float4* xp = reinterpret_cast<const float4*>(g_xl + (size_t)s * HDc + base);
        float4 v0 = xp[0], v1 = xp[1];
        xlv[0]=v0.x; xlv[1]=v0.y; xlv[2]=v0.z; xlv[3]=v0.w;
        xlv[4]=v1.x; xlv[5]=v1.y; xlv[6]=v1.z; xlv[7]=v1.w;

        const float* tab = isloop ? (s_lee + base) : (g_table + (size_t)t * HDc + base);
        float part = 0.f;
        #pragma unroll
        for (int i = 0; i < 8; ++i) {
            float z = xlv[i] + s_xr[base + i] + tab[i];
            z = z > 0.f ? z : 0.2f * z;
            part = fmaf(z, s_att[base + i], part);
        }
        #pragma unroll
        for (int o = 16; o > 0; o >>= 1)
            part += __shfl_xor_sync(0xffffffffu, part, o);

        float mn = fmaxf(m, part);
        float sc = __expf(m - mn);
        float p  = __expf(part - mn);
        d = d * sc + p;
        #pragma unroll
        for (int i = 0; i < 8; ++i) acc[i] = fmaf(acc[i], sc, p * xlv[i]);
        m = mn;
    }

    float invd = 1.0f / d;
    #pragma unroll
    for (int i = 0; i < 8; ++i) s_out[base + i] = acc[i] * invd;
    __syncthreads();

    {
        int c = tid;
        float v = 0.f;
        #pragma unroll
        for (int h = 0; h < HHc; ++h) v += s_out[h * DHc + c];
        v = fmaf(v, 0.125f, bgat_l[c]);
        hout[(size_t)n * DHc + c] = fmaxf(v, 0.f);
    }
}

// ---------------- host orchestration ----------------
extern "C" void kernel_launch(void* const* d_in, const int* in_sizes, int n_in,
                              void* d_out, int out_size) {
    const float* x         = (const float*)d_in[0];
    const int*   edge_index= (const int*)  d_in[1];
    const int*   edge_attr = (const int*)  d_in[2];
    const int*   node_types= (const int*)  d_in[3];
    const float* W_in      = (const float*)d_in[4];
    const float* b_in      = (const float*)d_in[5];
    const float* node_emb  = (const float*)d_in[6];
    const float* edge_emb  = (const float*)d_in[7];
    const float* Wl        = (const float*)d_in[8];
    const float* bl        = (const float*)d_in[9];
    const float* Wr        = (const float*)d_in[10];
    const float* br        = (const float*)d_in[11];
    const float* We        = (const float*)d_in[12];
    const float* att       = (const float*)d_in[13];
    const float* b_gat     = (const float*)d_in[14];
    const float* W_out     = (const float*)d_in[15];
    const float* b_out     = (const float*)d_in[16];
    float* out = (float*)d_out;

    float* h_base;  cudaGetSymbolAddress((void**)&h_base, g_h);
    float* xl;      cudaGetSymbolAddress((void**)&xl, g_xl);
    float* xr;      cudaGetSymbolAddress((void**)&xr, g_xr);
    __nv_bfloat16* Apk; cudaGetSymbolAddress((void**)&Apk, g_Apack);
    __nv_bfloat16* Bpk; cudaGetSymbolAddress((void**)&Bpk, g_Bpack);

    cudaFuncSetAttribute(k_gemm_mma, cudaFuncAttributeMaxDynamicSharedMemorySize, GEMM_SMEM);

    // CSR + histogram
    k_zero<<<(Nn * NTc + 255) / 256, 256>>>();
    k_count<<<(Ee + 255) / 256, 256>>>(edge_index, edge_attr);
    k_scan<<<1, 256>>>();
    k_fill<<<(Ee + 255) / 256, 256>>>(edge_index);
    k_sort<<<(Nn + 255) / 256, 256>>>();

    // pack all weights (transposed, bf16 hi/lo)
    k_pack_w<<<dim3(DHc / 32, DINc / 32), 256>>>(W_in, Bpk + OFF_WIN, DINc, DHc);
    for (int l = 0; l < LLc; ++l) {
        k_pack_w<<<dim3(HDc / 32, DHc / 32), 256>>>(Wl + (size_t)l * DHc * HDc,
                                                    Bpk + OFF_WL(l), DHc, HDc);
        k_pack_w<<<dim3(HDc / 32, DHc / 32), 256>>>(Wr + (size_t)l * DHc * HDc,
                                                    Bpk + OFF_WR(l), DHc, HDc);
    }
    k_pack_w<<<dim3(DHc / 32, DHc / 32), 256>>>(W_out, Bpk + OFF_WOUT, DHc, DHc);

    // input projection: h0 = x @ W_in + b_in + node_emb[types]
    k_pack_a<<<(Nn * DINc) / 256, 256>>>(x, Apk, DINc);
    k_gemm_mma<<<dim3(DHc / 128, Nn / 128), 256, GEMM_SMEM>>>(
        Apk, Bpk + OFF_WIN, b_in, h_base, 3 * DINc, DHc, node_emb, node_types);

    int sel = 0;
    for (int l = 0; l < LLc; ++l) {
        const float* h_cur = h_base + (size_t)sel * Nn * DHc;
        float* h_nxt = h_base + (size_t)(sel ^ 1) * Nn * DHc;

        k_table<<<(NTc * HDc + 255) / 256, 256>>>(edge_emb, We + (size_t)l * DHc * HDc);
        k_pack_a<<<(Nn * DHc) / 256, 256>>>(h_cur, Apk, DHc);
        k_gemm_mma<<<dim3(HDc / 128, Nn / 128), 256, GEMM_SMEM>>>(
            Apk, Bpk + OFF_WL(l), bl + (size_t)l * HDc, xl, 3 * DHc, HDc, nullptr, nullptr);
        k_gemm_mma<<<dim3(HDc / 128, Nn / 128), 256, GEMM_SMEM>>>(
            Apk, Bpk + OFF_WR(l), br + (size_t)l * HDc, xr, 3 * DHc, HDc, nullptr, nullptr);
        k_edge<<<Nn, 256>>>(edge_index, edge_attr,
                            att + (size_t)l * HHc * DHc,
                            b_gat + (size_t)l * DHc, h_nxt);
        sel ^= 1;
    }

    // output projection
    {
        const float* h_cur = h_base + (size_t)sel * Nn * DHc;
        k_pack_a<<<(Nn * DHc) / 256, 256>>>(h_cur, Apk, DHc);
        k_gemm_mma<<<dim3(DHc / 128, Nn / 128), 256, GEMM_SMEM>>>(
            Apk, Bpk + OFF_WOUT, b_out, out, 3 * DHc, DHc, nullptr, nullptr);
    }
    (void)in_sizes; (void)n_in; (void)out_size;
}

// round 4
// speedup vs baseline: 1.7744x; 1.0841x over previous
#include <cuda_runtime.h>
#include <cuda_bf16.h>
#include <math.h>
#include <stdint.h>

// Problem constants
#define Nn   8192
#define Ee   32768
#define DINc 1024
#define DHc  256
#define HHc  8
#define LLc  3
#define HDc  2048   // H*DH
#define NTc  5
#define N2c  4096   // merged Wl|Wr output width

// ---------------- device scratch ----------------
__device__ float g_xlr[(size_t)Nn * N2c];          // merged xl|xr, 128MB
__device__ float g_table[NTc * HDc];
__device__ int   g_deg[Nn];
__device__ int   g_hist[Nn * NTc];
__device__ int   g_rowptr[Nn + 1];
__device__ int   g_woff[Nn];
__device__ int   g_eid[Ee];

__device__ __nv_bfloat16 g_Apack[(size_t)Nn * 3 * DINc];   // packed x [8192,3072]
__device__ __nv_bfloat16 g_hpack[(size_t)Nn * 3 * DHc];    // packed h [8192,768]
__device__ __nv_bfloat16 g_Bpack[10420224];                // packed weights

#define OFF_WIN  0
#define SZ_WIN   (DHc * 3 * DINc)                 // 786432
#define SZ_L     ((size_t)N2c * 3 * DHc)          // 3145728 (Wl|Wr merged)
#define OFF_WLR(l) (SZ_WIN + (size_t)(l) * SZ_L)
#define OFF_WOUT (SZ_WIN + (size_t)3 * SZ_L)

// ---------------- PTX helpers ----------------
__device__ __forceinline__ uint32_t smem_u32(const void* p) {
    uint32_t a;
    asm("{ .reg .u64 t; cvta.to.shared.u64 t, %1; cvt.u32.u64 %0, t; }" : "=r"(a) : "l"(p));
    return a;
}
__device__ __forceinline__ void cp16(uint32_t d, const void* g) {
    asm volatile("cp.async.cg.shared.global [%0], [%1], 16;" :: "r"(d), "l"(g));
}
__device__ __forceinline__ void ldsm_x4(uint32_t* r, uint32_t addr) {
    asm volatile("ldmatrix.sync.aligned.m8n8.x4.shared.b16 {%0,%1,%2,%3}, [%4];"
                 : "=r"(r[0]), "=r"(r[1]), "=r"(r[2]), "=r"(r[3]) : "r"(addr));
}
__device__ __forceinline__ void mma_bf16(float* c, const uint32_t* a, uint32_t b0, uint32_t b1) {
    asm volatile(
        "mma.sync.aligned.m16n8k16.row.col.f32.bf16.bf16.f32 "
        "{%0,%1,%2,%3}, {%4,%5,%6,%7}, {%8,%9}, {%0,%1,%2,%3};"
        : "+f"(c[0]), "+f"(c[1]), "+f"(c[2]), "+f"(c[3])
        : "r"(a[0]), "r"(a[1]), "r"(a[2]), "r"(a[3]), "r"(b0), "r"(b1));
}

// ---------------- CSR build ----------------
__global__ void k_zero() {
    int i = blockIdx.x * 256 + threadIdx.x;
    if (i < Nn) g_deg[i] = 0;
    if (i < Nn * NTc) g_hist[i] = 0;
}
__global__ void k_count(const int* __restrict__ ei, const int* __restrict__ ea) {
    int e = blockIdx.x * 256 + threadIdx.x;
    if (e < Ee) {
        int dst = ei[Ee + e];
        atomicAdd(&g_deg[dst], 1);
        atomicAdd(&g_hist[dst * NTc + ea[e]], 1);
    }
}
__global__ void k_scan() {
    __shared__ int part[256];
    int tid = threadIdx.x;
    int base = tid * 32;
    int s = 0;
    for (int i = 0; i < 32; ++i) s += g_deg[base + i];
    part[tid] = s;
    __syncthreads();
    for (int off = 1; off < 256; off <<= 1) {
        int v = (tid >= off) ? part[tid - off] : 0;
        __syncthreads();
        part[tid] += v;
        __syncthreads();
    }
    int run = (tid == 0) ? 0 : part[tid - 1];
    for (int i = 0; i < 32; ++i) {
        int n = base + i;
        g_rowptr[n] = run;
        g_woff[n] = run;
        run += g_deg[n];
    }
    if (tid == 255) g_rowptr[Nn] = run;
}
__global__ void k_fill(const int* __restrict__ ei) {
    int e = blockIdx.x * 256 + threadIdx.x;
    if (e < Ee) {
        int dst = ei[Ee + e];
        int pos = atomicAdd(&g_woff[dst], 1);
        g_eid[pos] = e;
    }
}
__global__ void k_sort() {
    int n = blockIdx.x * 256 + threadIdx.x;
    if (n < Nn) {
        int r0 = g_rowptr[n], r1 = g_rowptr[n + 1];
        for (int i = r0 + 1; i < r1; ++i) {
            int v = g_eid[i];
            int j = i - 1;
            while (j >= r0 && g_eid[j] > v) { g_eid[j + 1] = g_eid[j]; --j; }
            g_eid[j + 1] = v;
        }
    }
}

// ---------------- edge-type table ----------------
__global__ void k_table(const float* __restrict__ edge_emb,
                        const float* __restrict__ We_l) {
    int idx = blockIdx.x * 256 + threadIdx.x;
    if (idx < NTc * HDc) {
        int t = idx / HDc, j = idx % HDc;
        const float* w = We_l + j;
        const float* e = edge_emb + t * DHc;
        float s = 0.f;
        #pragma unroll 4
        for (int k = 0; k < DHc; ++k) s = fmaf(e[k], w[(size_t)k * HDc], s);
        g_table[idx] = s;
    }
}

// ---------------- packing (x only; h is packed in-epilogue) ----------------
__global__ void k_pack_a(const float* __restrict__ A, __nv_bfloat16* __restrict__ P, int K) {
    int idx = blockIdx.x * 256 + threadIdx.x;
    int m = idx / K, k = idx - m * K;
    float v = A[idx];
    __nv_bfloat16 hi = __float2bfloat16(v);
    __nv_bfloat16 lo = __float2bfloat16(v - __bfloat162float(hi));
    size_t b = (size_t)m * 3 * K;
    P[b + k]         = hi;
    P[b + K + k]     = lo;
    P[b + 2 * K + k] = hi;
}
// W[K,N] fp32 -> P[N, 3K] bf16 [hi|hi|lo] (transposed)
__global__ void k_pack_w(const float* __restrict__ W, __nv_bfloat16* __restrict__ P,
                         int K, int N) {
    __shared__ float t[32][33];
    int nb = blockIdx.x, kb = blockIdx.y;
    int tx = threadIdx.x & 31;
    int ty = threadIdx.x >> 5;
    #pragma unroll
    for (int i = 0; i < 32; i += 8)
        t[ty + i][tx] = W[(size_t)(kb * 32 + ty + i) * N + nb * 32 + tx];
    __syncthreads();
    int K3 = 3 * K;
    #pragma unroll
    for (int i = 0; i < 32; i += 8) {
        int n = nb * 32 + ty + i;
        int k = kb * 32 + tx;
        float v = t[tx][ty + i];
        __nv_bfloat16 hi = __float2bfloat16(v);
        __nv_bfloat16 lo = __float2bfloat16(v - __bfloat162float(hi));
        P[(size_t)n * K3 + k]         = hi;
        P[(size_t)n * K3 + K + k]     = hi;
        P[(size_t)n * K3 + 2 * K + k] = lo;
    }
}

// ---------------- mma.sync bf16 GEMM ----------------
// C[M,Nc] = A[M,Ktot] @ B[Nc,Ktot]^T (+bias, +emb). CTA 128x128, warp 32x64,
// BK=64 bf16 (128B SW128 rows), 3-stage cp.async, ONE sync per chunk, 2 CTAs/SM.
// If packA != null: also/instead write bf16 [hi|lo|hi] rows (stride 3*Nc).
#define GSTAGE 3
#define STG_BYTES 32768
#define GEMM_SMEM (GSTAGE * STG_BYTES)

__global__ void __launch_bounds__(256, 2)
k_gemm_mma(const __nv_bfloat16* __restrict__ A, const __nv_bfloat16* __restrict__ B,
           const float* __restrict__ bias, const float* __restrict__ bias2, int halfN,
           float* __restrict__ C, int Ktot, int Nc,
           const float* __restrict__ emb, const int* __restrict__ types,
           __nv_bfloat16* __restrict__ packA) {
    extern __shared__ __align__(1024) char smem[];
    const uint32_t sb = smem_u32(smem);
    const int tid = threadIdx.x;
    const int lane = tid & 31, w = tid >> 5;
    const int wm = w & 3, wn = w >> 2;
    const int row0 = blockIdx.y * 128;
    const int col0 = blockIdx.x * 128;
    const int nch = Ktot >> 6;

    float acc[2][8][4];
    #pragma unroll
    for (int i = 0; i < 2; ++i)
        #pragma unroll
        for (int j = 0; j < 8; ++j)
            #pragma unroll
            for (int q = 0; q < 4; ++q) acc[i][j][q] = 0.f;

    uint32_t sm_off[4];
    const __nv_bfloat16* gA[4];
    const __nv_bfloat16* gB[4];
    #pragma unroll
    for (int u = 0; u < 4; ++u) {
        int i = tid + u * 256;
        int r = i >> 3, seg = i & 7;
        uint32_t off = (uint32_t)(r * 128 + seg * 16);
        sm_off[u] = off ^ ((off >> 3) & 0x70);
        gA[u] = A + (size_t)(row0 + r) * Ktot + (seg << 3);
        gB[u] = B + (size_t)(col0 + r) * Ktot + (seg << 3);
    }
    auto load_chunk = [&](int c) {
        const uint32_t s = sb + (uint32_t)((c % GSTAGE) * STG_BYTES);
        const int kof = c << 6;
        #pragma unroll
        for (int u = 0; u < 4; ++u) cp16(s + sm_off[u], gA[u] + kof);
        #pragma unroll
        for (int u = 0; u < 4; ++u) cp16(s + 16384 + sm_off[u], gB[u] + kof);
        asm volatile("cp.async.commit_group;");
    };

    #pragma unroll
    for (int c = 0; c < GSTAGE - 1; ++c) load_chunk(c);

    uint32_t a_base[2], a_swz[2];
    #pragma unroll
    for (int mb = 0; mb < 2; ++mb) {
        int row = wm * 32 + mb * 16 + (lane & 15);
        a_base[mb] = (uint32_t)(row * 128 + ((lane >> 4) << 4));
        a_swz[mb] = (uint32_t)((row & 7) << 4);
    }
    uint32_t b_base[4], b_swz[4];
    #pragma unroll
    for (int nb = 0; nb < 4; ++nb) {
        int row = wn * 64 + nb * 16 + (lane & 7) + ((lane >> 4) << 3);
        b_base[nb] = (uint32_t)(row * 128 + (((lane >> 3) & 1) << 4));
        b_swz[nb] = (uint32_t)((row & 7) << 4);
    }

    for (int c = 0; c < nch; ++c) {
        asm volatile("cp.async.wait_group %0;" :: "n"(GSTAGE - 2));
        __syncthreads();
        if (c + GSTAGE - 1 < nch) load_chunk(c + GSTAGE - 1);
        else asm volatile("cp.async.commit_group;");
        const uint32_t stb = sb + (uint32_t)((c % GSTAGE) * STG_BYTES);
        #pragma unroll
        for (int kk = 0; kk < 4; ++kk) {
            const uint32_t kby = (uint32_t)(kk * 32);
            uint32_t a[2][4];
            #pragma unroll
            for (int mb = 0; mb < 2; ++mb)
                ldsm_x4(a[mb], stb + ((a_base[mb] + kby) ^ a_swz[mb]));
            uint32_t b[4][4];
            #pragma unroll
            for (int nb = 0; nb < 4; ++nb)
                ldsm_x4(b[nb], stb + 16384 + ((b_base[nb] + kby) ^ b_swz[nb]));
            #pragma unroll
            for (int mb = 0; mb < 2; ++mb)
                #pragma unroll
                for (int nb = 0; nb < 4; ++nb) {
                    mma_bf16(acc[mb][2 * nb],     a[mb], b[nb][0], b[nb][1]);
                    mma_bf16(acc[mb][2 * nb + 1], a[mb], b[nb][2], b[nb][3]);
                }
        }
    }

    // epilogue
    const float* bp = bias;
    int cadj = 0;
    if (bias2 && col0 >= halfN) { bp = bias2; cadj = halfN; }
    const int r_base = row0 + wm * 32 + (lane >> 2);
    const int c_base = col0 + wn * 64 + ((lane & 3) << 1);
    const int K3 = 3 * Nc;
    #pragma unroll
    for (int mb = 0; mb < 2; ++mb) {
        const int r1 = r_base + mb * 16;
        const int r2 = r1 + 8;
        #pragma unroll
        for (int nt = 0; nt < 8; ++nt) {
            const int col = c_base + nt * 8;
            float bx = bp[col - cadj], by = bp[col + 1 - cadj];
            float e1x = 0.f, e1y = 0.f, e2x = 0.f, e2y = 0.f;
            if (emb) {
                const float* em1 = emb + (size_t)types[r1] * Nc + col;
                const float* em2 = emb + (size_t)types[r2] * Nc + col;
                e1x = em1[0]; e1y = em1[1]; e2x = em2[0]; e2y = em2[1];
            }
            float v00 = acc[mb][nt][0] + bx + e1x;
            float v01 = acc[mb][nt][1] + by + e1y;
            float v10 = acc[mb][nt][2] + bx + e2x;
            float v11 = acc[mb][nt][3] + by + e2y;
            if (C) {
                float2 t0 = {v00, v01}, t1 = {v10, v11};
                *reinterpret_cast<float2*>(&C[(size_t)r1 * Nc + col]) = t0;
                *reinterpret_cast<float2*>(&C[(size_t)r2 * Nc + col]) = t1;
            }
            if (packA) {
                __nv_bfloat16 h00 = __float2bfloat16(v00);
                __nv_bfloat16 h01 = __float2bfloat16(v01);
                __nv_bfloat16 h10 = __float2bfloat16(v10);
                __nv_bfloat16 h11 = __float2bfloat16(v11);
                __nv_bfloat162 hp1 = {h00, h01};
                __nv_bfloat162 hp2 = {h10, h11};
                __nv_bfloat162 lp1 = {__float2bfloat16(v00 - __bfloat162float(h00)),
                                      __float2bfloat16(v01 - __bfloat162float(h01))};
                __nv_bfloat162 lp2 = {__float2bfloat16(v10 - __bfloat162float(h10)),
                                      __float2bfloat16(v11 - __bfloat162float(h11))};
                __nv_bfloat16* p1 = packA + (size_t)r1 * K3 + col;
                __nv_bfloat16* p2 = packA + (size_t)r2 * K3 + col;
                *reinterpret_cast<__nv_bfloat162*>(p1)          = hp1;
                *reinterpret_cast<__nv_bfloat162*>(p1 + Nc)     = lp1;
                *reinterpret_cast<__nv_bfloat162*>(p1 + 2 * Nc) = hp1;
                *reinterpret_cast<__nv_bfloat162*>(p2)          = hp2;
                *reinterpret_cast<__nv_bfloat162*>(p2 + Nc)     = lp2;
                *reinterpret_cast<__nv_bfloat162*>(p2 + 2 * Nc) = hp2;
            }
        }
    }
}

// ---------------- fused GATv2 edge kernel -> packed bf16 h ----------------
__global__ void __launch_bounds__(256)
k_edge(const int* __restrict__ edge_index, const int* __restrict__ edge_attr,
       const float* __restrict__ att_l, const float* __restrict__ bgat_l,
       __nv_bfloat16* __restrict__ packH) {
    const int n = blockIdx.x;
    const int tid = threadIdx.x;
    const int lane = tid & 31;
    const int base = ((tid >> 5) << 8) + (lane << 3);

    __shared__ float s_xr[HDc];
    __shared__ float s_att[HDc];
    __shared__ float s_lee[HDc];
    __shared__ float s_out[HDc];

    const int r0 = g_rowptr[n], r1 = g_rowptr[n + 1];
    const int deg = r1 - r0;
    const float inv = 1.0f / (float)(deg > 1 ? deg : 1);

    float c0 = (float)g_hist[n * NTc + 0];
    float c1 = (float)g_hist[n * NTc + 1];
    float c2 = (float)g_hist[n * NTc + 2];
    float c3 = (float)g_hist[n * NTc + 3];
    float c4 = (float)g_hist[n * NTc + 4];

    const float* xr_row = g_xlr + (size_t)n * N2c + HDc;   // xr half
    #pragma unroll
    for (int u = 0; u < 8; ++u) {
        int j = tid + u * 256;
        s_xr[j] = xr_row[j];
        s_att[j] = att_l[j];
        float v = c0 * g_table[0 * HDc + j];
        v = fmaf(c1, g_table[1 * HDc + j], v);
        v = fmaf(c2, g_table[2 * HDc + j], v);
        v = fmaf(c3, g_table[3 * HDc + j], v);
        v = fmaf(c4, g_table[4 * HDc + j], v);
        s_lee[j] = v * inv;
    }
    __syncthreads();

    float m = -1e30f, d = 0.f;
    float acc[8];
    #pragma unroll
    for (int i = 0; i < 8; ++i) acc[i] = 0.f;

    for (int idx = r0; idx <= r1; ++idx) {
        int s, t = 0;
        bool isloop = (idx == r1);
        if (isloop) {
            s = n;
        } else {
            int eid = g_eid[idx];
            s = edge_index[eid];
            t = edge_attr[eid];
        }
        float xlv[8];
        const float4* xp = reinterpret_cast<const float4*>(g_xlr + (size_t)s * N2c + base);
        float4 v0 = xp[0], v1 = xp[1];
        xlv[0]=v0.x; xlv[1]=v0.y; xlv[2]=v0.z; xlv[3]=v0.w;
        xlv[4]=v1.x; xlv[5]=v1.y; xlv[6]=v1.z; xlv[7]=v1.w;

        const float* tab = isloop ? (s_lee + base) : (g_table + (size_t)t * HDc + base);
        float part = 0.f;
        #pragma unroll
        for (int i = 0; i < 8; ++i) {
            float z = xlv[i] + s_xr[base + i] + tab[i];
            z = z > 0.f ? z : 0.2f * z;
            part = fmaf(z, s_att[base + i], part);
        }
        #pragma unroll
        for (int o = 16; o > 0; o >>= 1)
            part += __shfl_xor_sync(0xffffffffu, part, o);

        float mn = fmaxf(m, part);
        float sc = __expf(m - mn);
        float p  = __expf(part - mn);
        d = d * sc + p;
        #pragma unroll
        for (int i = 0; i < 8; ++i) acc[i] = fmaf(acc[i], sc, p * xlv[i]);
        m = mn;
    }

    float invd = 1.0f / d;
    #pragma unroll
    for (int i = 0; i < 8; ++i) s_out[base + i] = acc[i] * invd;
    __syncthreads();

    {
        int c = tid;
        float v = 0.f;
        #pragma unroll
        for (int h = 0; h < HHc; ++h) v += s_out[h * DHc + c];
        v = fmaf(v, 0.125f, bgat_l[c]);
        v = fmaxf(v, 0.f);
        __nv_bfloat16 hi = __float2bfloat16(v);
        __nv_bfloat16 lo = __float2bfloat16(v - __bfloat162float(hi));
        __nv_bfloat16* p = packH + (size_t)n * (3 * DHc) + c;
        p[0]        = hi;
        p[DHc]      = lo;
        p[2 * DHc]  = hi;
    }
}

// ---------------- host orchestration ----------------
extern "C" void kernel_launch(void* const* d_in, const int* in_sizes, int n_in,
                              void* d_out, int out_size) {
    const float* x         = (const float*)d_in[0];
    const int*   edge_index= (const int*)  d_in[1];
    const int*   edge_attr = (const int*)  d_in[2];
    const int*   node_types= (const int*)  d_in[3];
    const float* W_in      = (const float*)d_in[4];
    const float* b_in      = (const float*)d_in[5];
    const float* node_emb  = (const float*)d_in[6];
    const float* edge_emb  = (const float*)d_in[7];
    const float* Wl        = (const float*)d_in[8];
    const float* bl        = (const float*)d_in[9];
    const float* Wr        = (const float*)d_in[10];
    const float* br        = (const float*)d_in[11];
    const float* We        = (const float*)d_in[12];
    const float* att       = (const float*)d_in[13];
    const float* b_gat     = (const float*)d_in[14];
    const float* W_out     = (const float*)d_in[15];
    const float* b_out     = (const float*)d_in[16];
    float* out = (float*)d_out;

    float* xlr;     cudaGetSymbolAddress((void**)&xlr, g_xlr);
    __nv_bfloat16* Apk; cudaGetSymbolAddress((void**)&Apk, g_Apack);
    __nv_bfloat16* Hpk; cudaGetSymbolAddress((void**)&Hpk, g_hpack);
    __nv_bfloat16* Bpk; cudaGetSymbolAddress((void**)&Bpk, g_Bpack);

    cudaFuncSetAttribute(k_gemm_mma, cudaFuncAttributeMaxDynamicSharedMemorySize, GEMM_SMEM);

    // CSR + histogram
    k_zero<<<(Nn * NTc + 255) / 256, 256>>>();
    k_count<<<(Ee + 255) / 256, 256>>>(edge_index, edge_attr);
    k_scan<<<1, 256>>>();
    k_fill<<<(Ee + 255) / 256, 256>>>(edge_index);
    k_sort<<<(Nn + 255) / 256, 256>>>();

    // pack weights: W_in; merged [Wl|Wr] per layer; W_out
    k_pack_w<<<dim3(DHc / 32, DINc / 32), 256>>>(W_in, Bpk + OFF_WIN, DINc, DHc);
    for (int l = 0; l < LLc; ++l) {
        k_pack_w<<<dim3(HDc / 32, DHc / 32), 256>>>(Wl + (size_t)l * DHc * HDc,
                                                    Bpk + OFF_WLR(l), DHc, HDc);
        k_pack_w<<<dim3(HDc / 32, DHc / 32), 256>>>(Wr + (size_t)l * DHc * HDc,
                                                    Bpk + OFF_WLR(l) + (size_t)HDc * 3 * DHc,
                                                    DHc, HDc);
    }
    k_pack_w<<<dim3(DHc / 32, DHc / 32), 256>>>(W_out, Bpk + OFF_WOUT, DHc, DHc);

    // pack x
    k_pack_a<<<(Nn * DINc) / 256, 256>>>(x, Apk, DINc);

    // input projection: packed h0 directly (no fp32 h stored)
    k_gemm_mma<<<dim3(DHc / 128, Nn / 128), 256, GEMM_SMEM>>>(
        Apk, Bpk + OFF_WIN, b_in, nullptr, 0, nullptr, 3 * DINc, DHc,
        node_emb, node_types, Hpk);

    for (int l = 0; l < LLc; ++l) {
        k_table<<<(NTc * HDc + 255) / 256, 256>>>(edge_emb, We + (size_t)l * DHc * HDc);
        // merged xl|xr GEMM: [8192, 4096]
        k_gemm_mma<<<dim3(N2c / 128, Nn / 128), 256, GEMM_SMEM>>>(
            Hpk, Bpk + OFF_WLR(l), bl + (size_t)l * HDc, br + (size_t)l * HDc, HDc,
            xlr, 3 * DHc, N2c, nullptr, nullptr, nullptr);
        // edge aggregation -> packed h_{l+1}
        k_edge<<<Nn, 256>>>(edge_index, edge_attr,
                            att + (size_t)l * HHc * DHc,
                            b_gat + (size_t)l * DHc, Hpk);
    }

    // output projection -> d_out fp32
    k_gemm_mma<<<dim3(DHc / 128, Nn / 128), 256, GEMM_SMEM>>>(
        Hpk, Bpk + OFF_WOUT, b_out, nullptr, 0, out, 3 * DHc, DHc,
        nullptr, nullptr, nullptr);

    (void)in_sizes; (void)n_in; (void)out_size;
}

// round 5
// speedup vs baseline: 1.9092x; 1.0760x over previous
#include <cuda_runtime.h>
#include <cuda_bf16.h>
#include <math.h>
#include <stdint.h>

// Problem constants
#define Nn   8192
#define Ee   32768
#define DINc 1024
#define DHc  256
#define HHc  8
#define LLc  3
#define HDc  2048   // H*DH
#define NTc  5
#define N2c  4096   // merged Wl|Wr output width

// ---------------- device scratch ----------------
__device__ float g_xlr[(size_t)Nn * N2c];
__device__ float g_table[LLc * NTc * HDc];
__device__ int   g_deg[Nn];
__device__ int   g_hist[Nn * NTc];
__device__ int   g_rowptr[Nn + 1];
__device__ int   g_woff[Nn];
__device__ int   g_eid[Ee];

__device__ __nv_bfloat16 g_Apack[(size_t)Nn * 3 * DINc];
__device__ __nv_bfloat16 g_hpack[(size_t)Nn * 3 * DHc];
__device__ __nv_bfloat16 g_Bpack[10420224];

#define OFF_WIN  0
#define SZ_WIN   (DHc * 3 * DINc)
#define SZ_L     ((size_t)N2c * 3 * DHc)
#define OFF_WLR(l) (SZ_WIN + (size_t)(l) * SZ_L)
#define OFF_WOUT (SZ_WIN + (size_t)3 * SZ_L)

// ---------------- PTX helpers ----------------
__device__ __forceinline__ uint32_t smem_u32(const void* p) {
    uint32_t a;
    asm("{ .reg .u64 t; cvta.to.shared.u64 t, %1; cvt.u32.u64 %0, t; }" : "=r"(a) : "l"(p));
    return a;
}
__device__ __forceinline__ void cp16(uint32_t d, const void* g) {
    asm volatile("cp.async.cg.shared.global [%0], [%1], 16;" :: "r"(d), "l"(g));
}
__device__ __forceinline__ void ldsm_x4(uint32_t* r, uint32_t addr) {
    asm volatile("ldmatrix.sync.aligned.m8n8.x4.shared.b16 {%0,%1,%2,%3}, [%4];"
                 : "=r"(r[0]), "=r"(r[1]), "=r"(r[2]), "=r"(r[3]) : "r"(addr));
}
__device__ __forceinline__ void mma_bf16(float* c, const uint32_t* a, uint32_t b0, uint32_t b1) {
    asm volatile(
        "mma.sync.aligned.m16n8k16.row.col.f32.bf16.bf16.f32 "
        "{%0,%1,%2,%3}, {%4,%5,%6,%7}, {%8,%9}, {%0,%1,%2,%3};"
        : "+f"(c[0]), "+f"(c[1]), "+f"(c[2]), "+f"(c[3])
        : "r"(a[0]), "r"(a[1]), "r"(a[2]), "r"(a[3]), "r"(b0), "r"(b1));
}

// ---------------- CSR build ----------------
__global__ void k_zero() {
    int i = blockIdx.x * 256 + threadIdx.x;
    if (i < Nn) g_deg[i] = 0;
    if (i < Nn * NTc) g_hist[i] = 0;
}
__global__ void k_count(const int* __restrict__ ei, const int* __restrict__ ea) {
    int e = blockIdx.x * 256 + threadIdx.x;
    if (e < Ee) {
        int dst = ei[Ee + e];
        atomicAdd(&g_deg[dst], 1);
        atomicAdd(&g_hist[dst * NTc + ea[e]], 1);
    }
}
__global__ void k_scan() {
    __shared__ int part[256];
    int tid = threadIdx.x;
    int base = tid * 32;
    int s = 0;
    for (int i = 0; i < 32; ++i) s += g_deg[base + i];
    part[tid] = s;
    __syncthreads();
    for (int off = 1; off < 256; off <<= 1) {
        int v = (tid >= off) ? part[tid - off] : 0;
        __syncthreads();
        part[tid] += v;
        __syncthreads();
    }
    int run = (tid == 0) ? 0 : part[tid - 1];
    for (int i = 0; i < 32; ++i) {
        int n = base + i;
        g_rowptr[n] = run;
        g_woff[n] = run;
        run += g_deg[n];
    }
    if (tid == 255) g_rowptr[Nn] = run;
}
__global__ void k_fill(const int* __restrict__ ei) {
    int e = blockIdx.x * 256 + threadIdx.x;
    if (e < Ee) {
        int dst = ei[Ee + e];
        int pos = atomicAdd(&g_woff[dst], 1);
        g_eid[pos] = e;
    }
}
__global__ void k_sort() {
    int n = blockIdx.x * 256 + threadIdx.x;
    if (n < Nn) {
        int r0 = g_rowptr[n], r1 = g_rowptr[n + 1];
        for (int i = r0 + 1; i < r1; ++i) {
            int v = g_eid[i];
            int j = i - 1;
            while (j >= r0 && g_eid[j] > v) { g_eid[j + 1] = g_eid[j]; --j; }
            g_eid[j + 1] = v;
        }
    }
}

// ---------------- fused packing: x, all weights, all tables ----------------
// block ranges: [0,8192) x-rows | [8192,8448) W_in tiles | [8448,11520) Wl/Wr tiles
//               [11520,11584) W_out tiles | [11584,11704) table segments
__global__ void __launch_bounds__(256)
k_pack_all(const float* __restrict__ x,
           const float* __restrict__ W_in,
           const float* __restrict__ Wl, const float* __restrict__ Wr,
           const float* __restrict__ W_out,
           const float* __restrict__ edge_emb, const float* __restrict__ We,
           __nv_bfloat16* __restrict__ Apk, __nv_bfloat16* __restrict__ Bpk) {
    const int bid = blockIdx.x;
    const int tid = threadIdx.x;

    if (bid < Nn) {
        // pack x row -> [hi|lo|hi]
        const float4 v = *reinterpret_cast<const float4*>(x + (size_t)bid * DINc + tid * 4);
        __nv_bfloat16 h0 = __float2bfloat16(v.x), h1 = __float2bfloat16(v.y);
        __nv_bfloat16 h2 = __float2bfloat16(v.z), h3 = __float2bfloat16(v.w);
        __nv_bfloat162 hp0 = {h0, h1}, hp1 = {h2, h3};
        __nv_bfloat162 lp0 = {__float2bfloat16(v.x - __bfloat162float(h0)),
                              __float2bfloat16(v.y - __bfloat162float(h1))};
        __nv_bfloat162 lp1 = {__float2bfloat16(v.z - __bfloat162float(h2)),
                              __float2bfloat16(v.w - __bfloat162float(h3))};
        __nv_bfloat16* p = Apk + (size_t)bid * 3 * DINc + tid * 4;
        reinterpret_cast<__nv_bfloat162*>(p)[0] = hp0;
        reinterpret_cast<__nv_bfloat162*>(p)[1] = hp1;
        reinterpret_cast<__nv_bfloat162*>(p + DINc)[0] = lp0;
        reinterpret_cast<__nv_bfloat162*>(p + DINc)[1] = lp1;
        reinterpret_cast<__nv_bfloat162*>(p + 2 * DINc)[0] = hp0;
        reinterpret_cast<__nv_bfloat162*>(p + 2 * DINc)[1] = hp1;
        return;
    }
    if (bid < Nn + 256 + 3072 + 64) {
        // weight tile pack: 32x32 transpose, [hi|hi|lo]
        const float* W; __nv_bfloat16* P; int K, N, nb, kb;
        int id = bid - Nn;
        if (id < 256) {
            W = W_in; P = Bpk + OFF_WIN; K = DINc; N = DHc;
            nb = id & 7; kb = id >> 3;
        } else if (id < 256 + 3072) {
            int id2 = id - 256;
            int mat = id2 >> 9;          // 0..5
            int t = id2 & 511;
            int l = mat >> 1, side = mat & 1;
            W = (side == 0 ? Wl : Wr) + (size_t)l * DHc * HDc;
            P = Bpk + OFF_WLR(l) + (size_t)side * HDc * 3 * DHc;
            K = DHc; N = HDc;
            nb = t & 63; kb = t >> 6;
        } else {
            int id2 = id - 256 - 3072;
            W = W_out; P = Bpk + OFF_WOUT; K = DHc; N = DHc;
            nb = id2 & 7; kb = id2 >> 3;
        }
        __shared__ float tbuf[32][33];
        int tx = tid & 31, ty = tid >> 5;
        #pragma unroll
        for (int i = 0; i < 32; i += 8)
            tbuf[ty + i][tx] = W[(size_t)(kb * 32 + ty + i) * N + nb * 32 + tx];
        __syncthreads();
        int K3 = 3 * K;
        #pragma unroll
        for (int i = 0; i < 32; i += 8) {
            int n = nb * 32 + ty + i;
            int k = kb * 32 + tx;
            float v = tbuf[tx][ty + i];
            __nv_bfloat16 hi = __float2bfloat16(v);
            __nv_bfloat16 lo = __float2bfloat16(v - __bfloat162float(hi));
            P[(size_t)n * K3 + k]         = hi;
            P[(size_t)n * K3 + K + k]     = hi;
            P[(size_t)n * K3 + 2 * K + k] = lo;
        }
        return;
    }
    {
        // tables: table[l][t][j] = edge_emb[t] . We[l][:,j]
        int id = bid - (Nn + 256 + 3072 + 64);   // 0..119
        int lt = id >> 3;                          // 0..14
        int jb = id & 7;
        int l = lt / NTc, t = lt % NTc;
        int j = jb * 256 + tid;
        const float* w = We + (size_t)l * DHc * HDc + j;
        const float* e = edge_emb + t * DHc;
        float s = 0.f;
        #pragma unroll 4
        for (int k = 0; k < DHc; ++k) s = fmaf(e[k], w[(size_t)k * HDc], s);
        g_table[(size_t)l * NTc * HDc + t * HDc + j] = s;
    }
}

// ---------------- GEMM kernel 1 (proj): CTA 128x128, warp 32x64, 3-stage, 2 CTA/SM ----
#define GSTAGE 3
#define STG_BYTES 32768
#define GEMM_SMEM (GSTAGE * STG_BYTES)

__global__ void __launch_bounds__(256, 2)
k_gemm_mma(const __nv_bfloat16* __restrict__ A, const __nv_bfloat16* __restrict__ B,
           const float* __restrict__ bias, float* __restrict__ C, int Ktot, int Nc,
           const float* __restrict__ emb, const int* __restrict__ types,
           __nv_bfloat16* __restrict__ packA) {
    extern __shared__ __align__(1024) char smem[];
    const uint32_t sb = smem_u32(smem);
    const int tid = threadIdx.x;
    const int lane = tid & 31, w = tid >> 5;
    const int wm = w & 3, wn = w >> 2;
    const int row0 = blockIdx.y * 128;
    const int col0 = blockIdx.x * 128;
    const int nch = Ktot >> 6;

    float acc[2][8][4];
    #pragma unroll
    for (int i = 0; i < 2; ++i)
        #pragma unroll
        for (int j = 0; j < 8; ++j)
            #pragma unroll
            for (int q = 0; q < 4; ++q) acc[i][j][q] = 0.f;

    uint32_t sm_off[4];
    const __nv_bfloat16* gA[4];
    const __nv_bfloat16* gB[4];
    #pragma unroll
    for (int u = 0; u < 4; ++u) {
        int i = tid + u * 256;
        int r = i >> 3, seg = i & 7;
        uint32_t off = (uint32_t)(r * 128 + seg * 16);
        sm_off[u] = off ^ ((off >> 3) & 0x70);
        gA[u] = A + (size_t)(row0 + r) * Ktot + (seg << 3);
        gB[u] = B + (size_t)(col0 + r) * Ktot + (seg << 3);
    }
    auto load_chunk = [&](int c) {
        const uint32_t s = sb + (uint32_t)((c % GSTAGE) * STG_BYTES);
        const int kof = c << 6;
        #pragma unroll
        for (int u = 0; u < 4; ++u) cp16(s + sm_off[u], gA[u] + kof);
        #pragma unroll
        for (int u = 0; u < 4; ++u) cp16(s + 16384 + sm_off[u], gB[u] + kof);
        asm volatile("cp.async.commit_group;");
    };
    #pragma unroll
    for (int c = 0; c < GSTAGE - 1; ++c) load_chunk(c);

    uint32_t a_base[2], a_swz[2];
    #pragma unroll
    for (int mb = 0; mb < 2; ++mb) {
        int row = wm * 32 + mb * 16 + (lane & 15);
        a_base[mb] = (uint32_t)(row * 128 + ((lane >> 4) << 4));
        a_swz[mb] = (uint32_t)((row & 7) << 4);
    }
    uint32_t b_base[4], b_swz[4];
    #pragma unroll
    for (int nb = 0; nb < 4; ++nb) {
        int row = wn * 64 + nb * 16 + (lane & 7) + ((lane >> 4) << 3);
        b_base[nb] = (uint32_t)(row * 128 + (((lane >> 3) & 1) << 4));
        b_swz[nb] = (uint32_t)((row & 7) << 4);
    }

    for (int c = 0; c < nch; ++c) {
        asm volatile("cp.async.wait_group %0;" :: "n"(GSTAGE - 2));
        __syncthreads();
        if (c + GSTAGE - 1 < nch) load_chunk(c + GSTAGE - 1);
        else asm volatile("cp.async.commit_group;");
        const uint32_t stb = sb + (uint32_t)((c % GSTAGE) * STG_BYTES);
        #pragma unroll
        for (int kk = 0; kk < 4; ++kk) {
            const uint32_t kby = (uint32_t)(kk * 32);
            uint32_t a[2][4];
            #pragma unroll
            for (int mb = 0; mb < 2; ++mb)
                ldsm_x4(a[mb], stb + ((a_base[mb] + kby) ^ a_swz[mb]));
            uint32_t b[4][4];
            #pragma unroll
            for (int nb = 0; nb < 4; ++nb)
                ldsm_x4(b[nb], stb + 16384 + ((b_base[nb] + kby) ^ b_swz[nb]));
            #pragma unroll
            for (int mb = 0; mb < 2; ++mb)
                #pragma unroll
                for (int nb = 0; nb < 4; ++nb) {
                    mma_bf16(acc[mb][2 * nb],     a[mb], b[nb][0], b[nb][1]);
                    mma_bf16(acc[mb][2 * nb + 1], a[mb], b[nb][2], b[nb][3]);
                }
        }
    }

    const int r_base = row0 + wm * 32 + (lane >> 2);
    const int c_base = col0 + wn * 64 + ((lane & 3) << 1);
    const int K3 = 3 * Nc;
    #pragma unroll
    for (int mb = 0; mb < 2; ++mb) {
        const int r1 = r_base + mb * 16;
        const int r2 = r1 + 8;
        #pragma unroll
        for (int nt = 0; nt < 8; ++nt) {
            const int col = c_base + nt * 8;
            float bx = bias[col], by = bias[col + 1];
            float e1x = 0.f, e1y = 0.f, e2x = 0.f, e2y = 0.f;
            if (emb) {
                const float* em1 = emb + (size_t)types[r1] * Nc + col;
                const float* em2 = emb + (size_t)types[r2] * Nc + col;
                e1x = em1[0]; e1y = em1[1]; e2x = em2[0]; e2y = em2[1];
            }
            float v00 = acc[mb][nt][0] + bx + e1x;
            float v01 = acc[mb][nt][1] + by + e1y;
            float v10 = acc[mb][nt][2] + bx + e2x;
            float v11 = acc[mb][nt][3] + by + e2y;
            if (C) {
                float2 t0 = {v00, v01}, t1 = {v10, v11};
                *reinterpret_cast<float2*>(&C[(size_t)r1 * Nc + col]) = t0;
                *reinterpret_cast<float2*>(&C[(size_t)r2 * Nc + col]) = t1;
            }
            if (packA) {
                __nv_bfloat16 h00 = __float2bfloat16(v00);
                __nv_bfloat16 h01 = __float2bfloat16(v01);
                __nv_bfloat16 h10 = __float2bfloat16(v10);
                __nv_bfloat16 h11 = __float2bfloat16(v11);
                __nv_bfloat162 hp1 = {h00, h01};
                __nv_bfloat162 hp2 = {h10, h11};
                __nv_bfloat162 lp1 = {__float2bfloat16(v00 - __bfloat162float(h00)),
                                      __float2bfloat16(v01 - __bfloat162float(h01))};
                __nv_bfloat162 lp2 = {__float2bfloat16(v10 - __bfloat162float(h10)),
                                      __float2bfloat16(v11 - __bfloat162float(h11))};
                __nv_bfloat16* p1 = packA + (size_t)r1 * K3 + col;
                __nv_bfloat16* p2 = packA + (size_t)r2 * K3 + col;
                *reinterpret_cast<__nv_bfloat162*>(p1)          = hp1;
                *reinterpret_cast<__nv_bfloat162*>(p1 + Nc)     = lp1;
                *reinterpret_cast<__nv_bfloat162*>(p1 + 2 * Nc) = hp1;
                *reinterpret_cast<__nv_bfloat162*>(p2)          = hp2;
                *reinterpret_cast<__nv_bfloat162*>(p2 + Nc)     = lp2;
                *reinterpret_cast<__nv_bfloat162*>(p2 + 2 * Nc) = hp2;
            }
        }
    }
}

// ---------------- GEMM kernel 2 (merged xl|xr): CTA 128x256, warp 64x64, 3-stage ----
#define BSTG_BYTES 49152          // A 16KB + B 32KB
#define BGEMM_SMEM (GSTAGE * BSTG_BYTES)

__global__ void __launch_bounds__(256, 1)
k_gemm_big(const __nv_bfloat16* __restrict__ A, const __nv_bfloat16* __restrict__ B,
           const float* __restrict__ bias, const float* __restrict__ bias2, int halfN,
           float* __restrict__ C, int Ktot, int Nc) {
    extern __shared__ __align__(1024) char smem[];
    const uint32_t sb = smem_u32(smem);
    const int tid = threadIdx.x;
    const int lane = tid & 31, w = tid >> 5;
    const int wm = w & 1, wn = w >> 1;
    const int row0 = blockIdx.y * 128;
    const int col0 = blockIdx.x * 256;
    const int nch = Ktot >> 6;

    float acc[4][8][4];
    #pragma unroll
    for (int i = 0; i < 4; ++i)
        #pragma unroll
        for (int j = 0; j < 8; ++j)
            #pragma unroll
            for (int q = 0; q < 4; ++q) acc[i][j][q] = 0.f;

    uint32_t sm_offA[4], sm_offB[8];
    const __nv_bfloat16* gA[4];
    const __nv_bfloat16* gB[8];
    #pragma unroll
    for (int u = 0; u < 4; ++u) {
        int i = tid + u * 256;
        int r = i >> 3, seg = i & 7;
        uint32_t off = (uint32_t)(r * 128 + seg * 16);
        sm_offA[u] = off ^ ((off >> 3) & 0x70);
        gA[u] = A + (size_t)(row0 + r) * Ktot + (seg << 3);
    }
    #pragma unroll
    for (int u = 0; u < 8; ++u) {
        int i = tid + u * 256;
        int r = i >> 3, seg = i & 7;
        uint32_t off = (uint32_t)(r * 128 + seg * 16);
        sm_offB[u] = off ^ ((off >> 3) & 0x70);
        gB[u] = B + (size_t)(col0 + r) * Ktot + (seg << 3);
    }
    auto load_chunk = [&](int c) {
        const uint32_t s = sb + (uint32_t)((c % GSTAGE) * BSTG_BYTES);
        const int kof = c << 6;
        #pragma unroll
        for (int u = 0; u < 4; ++u) cp16(s + sm_offA[u], gA[u] + kof);
        #pragma unroll
        for (int u = 0; u < 8; ++u) cp16(s + 16384 + sm_offB[u], gB[u] + kof);
        asm volatile("cp.async.commit_group;");
    };
    #pragma unroll
    for (int c = 0; c < GSTAGE - 1; ++c) load_chunk(c);

    uint32_t a_base[4], a_swz[4];
    #pragma unroll
    for (int mb = 0; mb < 4; ++mb) {
        int row = wm * 64 + mb * 16 + (lane & 15);
        a_base[mb] = (uint32_t)(row * 128 + ((lane >> 4) << 4));
        a_swz[mb] = (uint32_t)((row & 7) << 4);
    }
    uint32_t b_base[4], b_swz[4];
    #pragma unroll
    for (int nb = 0; nb < 4; ++nb) {
        int row = wn * 64 + nb * 16 + (lane & 7) + ((lane >> 4) << 3);
        b_base[nb] = (uint32_t)(row * 128 + (((lane >> 3) & 1) << 4));
        b_swz[nb] = (uint32_t)((row & 7) << 4);
    }

    for (int c = 0; c < nch; ++c) {
        asm volatile("cp.async.wait_group %0;" :: "n"(GSTAGE - 2));
        __syncthreads();
        if (c + GSTAGE - 1 < nch) load_chunk(c + GSTAGE - 1);
        else asm volatile("cp.async.commit_group;");
        const uint32_t stb = sb + (uint32_t)((c % GSTAGE) * BSTG_BYTES);
        #pragma unroll
        for (int kk = 0; kk < 4; ++kk) {
            const uint32_t kby = (uint32_t)(kk * 32);
            uint32_t a[4][4];
            #pragma unroll
            for (int mb = 0; mb < 4; ++mb)
                ldsm_x4(a[mb], stb + ((a_base[mb] + kby) ^ a_swz[mb]));
            uint32_t b[4][4];
            #pragma unroll
            for (int nb = 0; nb < 4; ++nb)
                ldsm_x4(b[nb], stb + 16384 + ((b_base[nb] + kby) ^ b_swz[nb]));
            #pragma unroll
            for (int mb = 0; mb < 4; ++mb)
                #pragma unroll
                for (int nb = 0; nb < 4; ++nb) {
                    mma_bf16(acc[mb][2 * nb],     a[mb], b[nb][0], b[nb][1]);
                    mma_bf16(acc[mb][2 * nb + 1], a[mb], b[nb][2], b[nb][3]);
                }
        }
    }

    const float* bp = bias;
    int cadj = 0;
    if (bias2 && col0 >= halfN) { bp = bias2; cadj = halfN; }
    const int r_base = row0 + wm * 64 + (lane >> 2);
    const int c_base = col0 + wn * 64 + ((lane & 3) << 1);
    #pragma unroll
    for (int mb = 0; mb < 4; ++mb) {
        const int r1 = r_base + mb * 16;
        const int r2 = r1 + 8;
        #pragma unroll
        for (int nt = 0; nt < 8; ++nt) {
            const int col = c_base + nt * 8;
            float bx = bp[col - cadj], by = bp[col + 1 - cadj];
            float2 t0 = {acc[mb][nt][0] + bx, acc[mb][nt][1] + by};
            float2 t1 = {acc[mb][nt][2] + bx, acc[mb][nt][3] + by};
            *reinterpret_cast<float2*>(&C[(size_t)r1 * Nc + col]) = t0;
            *reinterpret_cast<float2*>(&C[(size_t)r2 * Nc + col]) = t1;
        }
    }
}

// ---------------- fused GATv2 edge kernel -> packed bf16 h ----------------
__global__ void __launch_bounds__(256)
k_edge(const int* __restrict__ edge_index, const int* __restrict__ edge_attr,
       const float* __restrict__ att_l, const float* __restrict__ bgat_l,
       int loff, __nv_bfloat16* __restrict__ packH) {
    const int n = blockIdx.x;
    const int tid = threadIdx.x;
    const int lane = tid & 31;
    const int base = ((tid >> 5) << 8) + (lane << 3);

    __shared__ float s_xr[HDc];
    __shared__ float s_att[HDc];
    __shared__ float s_lee[HDc];
    __shared__ float s_out[HDc];

    const int r0 = g_rowptr[n], r1 = g_rowptr[n + 1];
    const int deg = r1 - r0;
    const float inv = 1.0f / (float)(deg > 1 ? deg : 1);

    float c0 = (float)g_hist[n * NTc + 0];
    float c1 = (float)g_hist[n * NTc + 1];
    float c2 = (float)g_hist[n * NTc + 2];
    float c3 = (float)g_hist[n * NTc + 3];
    float c4 = (float)g_hist[n * NTc + 4];

    const float* tb = g_table + loff;
    const float* xr_row = g_xlr + (size_t)n * N2c + HDc;
    #pragma unroll
    for (int u = 0; u < 8; ++u) {
        int j = tid + u * 256;
        s_xr[j] = xr_row[j];
        s_att[j] = att_l[j];
        float v = c0 * tb[0 * HDc + j];
        v = fmaf(c1, tb[1 * HDc + j], v);
        v = fmaf(c2, tb[2 * HDc + j], v);
        v = fmaf(c3, tb[3 * HDc + j], v);
        v = fmaf(c4, tb[4 * HDc + j], v);
        s_lee[j] = v * inv;
    }
    __syncthreads();

    float m = -1e30f, d = 0.f;
    float acc[8];
    #pragma unroll
    for (int i = 0; i < 8; ++i) acc[i] = 0.f;

    for (int idx = r0; idx <= r1; ++idx) {
        int s, t = 0;
        bool isloop = (idx == r1);
        if (isloop) {
            s = n;
        } else {
            int eid = g_eid[idx];
            s = edge_index[eid];
            t = edge_attr[eid];
        }
        float xlv[8];
        const float4* xp = reinterpret_cast<const float4*>(g_xlr + (size_t)s * N2c + base);
        float4 v0 = xp[0], v1 = xp[1];
        xlv[0]=v0.x; xlv[1]=v0.y; xlv[2]=v0.z; xlv[3]=v0.w;
        xlv[4]=v1.x; xlv[5]=v1.y; xlv[6]=v1.z; xlv[7]=v1.w;

        const float* tab = isloop ? (s_lee + base) : (tb + (size_t)t * HDc + base);
        float part = 0.f;
        #pragma unroll
        for (int i = 0; i < 8; ++i) {
            float z = xlv[i] + s_xr[base + i] + tab[i];
            z = z > 0.f ? z : 0.2f * z;
            part = fmaf(z, s_att[base + i], part);
        }
        #pragma unroll
        for (int o = 16; o > 0; o >>= 1)
            part += __shfl_xor_sync(0xffffffffu, part, o);

        float mn = fmaxf(m, part);
        float sc = __expf(m - mn);
        float p  = __expf(part - mn);
        d = d * sc + p;
        #pragma unroll
        for (int i = 0; i < 8; ++i) acc[i] = fmaf(acc[i], sc, p * xlv[i]);
        m = mn;
    }

    float invd = 1.0f / d;
    #pragma unroll
    for (int i = 0; i < 8; ++i) s_out[base + i] = acc[i] * invd;
    __syncthreads();

    {
        int c = tid;
        float v = 0.f;
        #pragma unroll
        for (int h = 0; h < HHc; ++h) v += s_out[h * DHc + c];
        v = fmaf(v, 0.125f, bgat_l[c]);
        v = fmaxf(v, 0.f);
        __nv_bfloat16 hi = __float2bfloat16(v);
        __nv_bfloat16 lo = __float2bfloat16(v - __bfloat162float(hi));
        __nv_bfloat16* p = packH + (size_t)n * (3 * DHc) + c;
        p[0]        = hi;
        p[DHc]      = lo;
        p[2 * DHc]  = hi;
    }
}

// ---------------- host orchestration ----------------
extern "C" void kernel_launch(void* const* d_in, const int* in_sizes, int n_in,
                              void* d_out, int out_size) {
    const float* x         = (const float*)d_in[0];
    const int*   edge_index= (const int*)  d_in[1];
    const int*   edge_attr = (const int*)  d_in[2];
    const int*   node_types= (const int*)  d_in[3];
    const float* W_in      = (const float*)d_in[4];
    const float* b_in      = (const float*)d_in[5];
    const float* node_emb  = (const float*)d_in[6];
    const float* edge_emb  = (const float*)d_in[7];
    const float* Wl        = (const float*)d_in[8];
    const float* bl        = (const float*)d_in[9];
    const float* Wr        = (const float*)d_in[10];
    const float* br        = (const float*)d_in[11];
    const float* We        = (const float*)d_in[12];
    const float* att       = (const float*)d_in[13];
    const float* b_gat     = (const float*)d_in[14];
    const float* W_out     = (const float*)d_in[15];
    const float* b_out     = (const float*)d_in[16];
    float* out = (float*)d_out;

    float* xlr;     cudaGetSymbolAddress((void**)&xlr, g_xlr);
    __nv_bfloat16* Apk; cudaGetSymbolAddress((void**)&Apk, g_Apack);
    __nv_bfloat16* Hpk; cudaGetSymbolAddress((void**)&Hpk, g_hpack);
    __nv_bfloat16* Bpk; cudaGetSymbolAddress((void**)&Bpk, g_Bpack);

    cudaFuncSetAttribute(k_gemm_mma, cudaFuncAttributeMaxDynamicSharedMemorySize, GEMM_SMEM);
    cudaFuncSetAttribute(k_gemm_big, cudaFuncAttributeMaxDynamicSharedMemorySize, BGEMM_SMEM);

    // 1: pack everything (weights, x, tables)
    k_pack_all<<<Nn + 256 + 3072 + 64 + 120, 256>>>(x, W_in, Wl, Wr, W_out,
                                                    edge_emb, We, Apk, Bpk);
    // 2: CSR zero (independent)
    k_zero<<<(Nn * NTc + 255) / 256, 256>>>();
    // 3: input projection -> packed h0
    k_gemm_mma<<<dim3(2, 64), 256, GEMM_SMEM>>>(
        Apk, Bpk + OFF_WIN, b_in, nullptr, 3 * DINc, DHc, node_emb, node_types, Hpk);
    // 4: merged xl|xr GEMM layer 0   <- ncu capture slot
    k_gemm_big<<<dim3(N2c / 256, 64), 256, BGEMM_SMEM>>>(
        Hpk, Bpk + OFF_WLR(0), bl, br, HDc, xlr, 3 * DHc, N2c);
    // 5-8: finish CSR
    k_count<<<(Ee + 255) / 256, 256>>>(edge_index, edge_attr);
    k_scan<<<1, 256>>>();
    k_fill<<<(Ee + 255) / 256, 256>>>(edge_index);
    k_sort<<<(Nn + 255) / 256, 256>>>();

    for (int l = 0; l < LLc; ++l) {
        if (l > 0) {
            k_gemm_big<<<dim3(N2c / 256, 64), 256, BGEMM_SMEM>>>(
                Hpk, Bpk + OFF_WLR(l), bl + (size_t)l * HDc, br + (size_t)l * HDc,
                HDc, xlr, 3 * DHc, N2c);
        }
        k_edge<<<Nn, 256>>>(edge_index, edge_attr,
                            att + (size_t)l * HHc * DHc,
                            b_gat + (size_t)l * DHc, l * NTc * HDc, Hpk);
    }

    // output projection -> d_out fp32
    k_gemm_mma<<<dim3(2, 64), 256, GEMM_SMEM>>>(
        Hpk, Bpk + OFF_WOUT, b_out, out, 3 * DHc, DHc, nullptr, nullptr, nullptr);

    (void)in_sizes; (void)n_in; (void)out_size;
}

// round 6
// speedup vs baseline: 2.0874x; 1.0933x over previous
#include <cuda_runtime.h>
#include <cuda_bf16.h>
#include <cuda_fp16.h>
#include <math.h>
#include <stdint.h>

// Problem constants
#define Nn   8192
#define Ee   32768
#define DINc 1024
#define DHc  256
#define HHc  8
#define LLc  3
#define HDc  2048   // H*DH
#define NTc  5
#define N2c  4096   // merged Wl|Wr output width

// ---------------- device scratch ----------------
__device__ __half g_xlr[(size_t)Nn * N2c];         // merged xl|xr, fp16, 64MB (L2-resident)
__device__ float g_table[LLc * NTc * HDc];
__device__ int   g_deg[Nn];
__device__ int   g_hist[Nn * NTc];
__device__ int   g_rowptr[Nn + 1];
__device__ int   g_woff[Nn];
__device__ int   g_eid[Ee];

__device__ __nv_bfloat16 g_Apack[(size_t)Nn * 3 * DINc];
__device__ __nv_bfloat16 g_hpack[(size_t)Nn * 3 * DHc];
__device__ __nv_bfloat16 g_Bpack[10420224];

#define OFF_WIN  0
#define SZ_WIN   (DHc * 3 * DINc)
#define SZ_L     ((size_t)N2c * 3 * DHc)
#define OFF_WLR(l) (SZ_WIN + (size_t)(l) * SZ_L)
#define OFF_WOUT (SZ_WIN + (size_t)3 * SZ_L)

// ---------------- PTX helpers ----------------
__device__ __forceinline__ uint32_t smem_u32(const void* p) {
    uint32_t a;
    asm("{ .reg .u64 t; cvta.to.shared.u64 t, %1; cvt.u32.u64 %0, t; }" : "=r"(a) : "l"(p));
    return a;
}
__device__ __forceinline__ void cp16(uint32_t d, const void* g) {
    asm volatile("cp.async.cg.shared.global [%0], [%1], 16;" :: "r"(d), "l"(g));
}
__device__ __forceinline__ void ldsm_x4(uint32_t* r, uint32_t addr) {
    asm volatile("ldmatrix.sync.aligned.m8n8.x4.shared.b16 {%0,%1,%2,%3}, [%4];"
                 : "=r"(r[0]), "=r"(r[1]), "=r"(r[2]), "=r"(r[3]) : "r"(addr));
}
__device__ __forceinline__ void mma_bf16(float* c, const uint32_t* a, uint32_t b0, uint32_t b1) {
    asm volatile(
        "mma.sync.aligned.m16n8k16.row.col.f32.bf16.bf16.f32 "
        "{%0,%1,%2,%3}, {%4,%5,%6,%7}, {%8,%9}, {%0,%1,%2,%3};"
        : "+f"(c[0]), "+f"(c[1]), "+f"(c[2]), "+f"(c[3])
        : "r"(a[0]), "r"(a[1]), "r"(a[2]), "r"(a[3]), "r"(b0), "r"(b1));
}

// ---------------- CSR build ----------------
__global__ void k_zero() {
    int i = blockIdx.x * 256 + threadIdx.x;
    if (i < Nn) g_deg[i] = 0;
    if (i < Nn * NTc) g_hist[i] = 0;
}
__global__ void k_count(const int* __restrict__ ei, const int* __restrict__ ea) {
    int e = blockIdx.x * 256 + threadIdx.x;
    if (e < Ee) {
        int dst = ei[Ee + e];
        atomicAdd(&g_deg[dst], 1);
        atomicAdd(&g_hist[dst * NTc + ea[e]], 1);
    }
}
__global__ void k_scan() {
    __shared__ int part[256];
    int tid = threadIdx.x;
    int base = tid * 32;
    int s = 0;
    for (int i = 0; i < 32; ++i) s += g_deg[base + i];
    part[tid] = s;
    __syncthreads();
    for (int off = 1; off < 256; off <<= 1) {
        int v = (tid >= off) ? part[tid - off] : 0;
        __syncthreads();
        part[tid] += v;
        __syncthreads();
    }
    int run = (tid == 0) ? 0 : part[tid - 1];
    for (int i = 0; i < 32; ++i) {
        int n = base + i;
        g_rowptr[n] = run;
        g_woff[n] = run;
        run += g_deg[n];
    }
    if (tid == 255) g_rowptr[Nn] = run;
}
__global__ void k_fill(const int* __restrict__ ei) {
    int e = blockIdx.x * 256 + threadIdx.x;
    if (e < Ee) {
        int dst = ei[Ee + e];
        int pos = atomicAdd(&g_woff[dst], 1);
        g_eid[pos] = e;
    }
}
__global__ void k_sort() {
    int n = blockIdx.x * 256 + threadIdx.x;
    if (n < Nn) {
        int r0 = g_rowptr[n], r1 = g_rowptr[n + 1];
        for (int i = r0 + 1; i < r1; ++i) {
            int v = g_eid[i];
            int j = i - 1;
            while (j >= r0 && g_eid[j] > v) { g_eid[j + 1] = g_eid[j]; --j; }
            g_eid[j + 1] = v;
        }
    }
}

// ---------------- fused packing: x, all weights, all tables ----------------
__global__ void __launch_bounds__(256)
k_pack_all(const float* __restrict__ x,
           const float* __restrict__ W_in,
           const float* __restrict__ Wl, const float* __restrict__ Wr,
           const float* __restrict__ W_out,
           const float* __restrict__ edge_emb, const float* __restrict__ We,
           __nv_bfloat16* __restrict__ Apk, __nv_bfloat16* __restrict__ Bpk) {
    const int bid = blockIdx.x;
    const int tid = threadIdx.x;

    if (bid < Nn) {
        const float4 v = *reinterpret_cast<const float4*>(x + (size_t)bid * DINc + tid * 4);
        __nv_bfloat16 h0 = __float2bfloat16(v.x), h1 = __float2bfloat16(v.y);
        __nv_bfloat16 h2 = __float2bfloat16(v.z), h3 = __float2bfloat16(v.w);
        __nv_bfloat162 hp0 = {h0, h1}, hp1 = {h2, h3};
        __nv_bfloat162 lp0 = {__float2bfloat16(v.x - __bfloat162float(h0)),
                              __float2bfloat16(v.y - __bfloat162float(h1))};
        __nv_bfloat162 lp1 = {__float2bfloat16(v.z - __bfloat162float(h2)),
                              __float2bfloat16(v.w - __bfloat162float(h3))};
        __nv_bfloat16* p = Apk + (size_t)bid * 3 * DINc + tid * 4;
        reinterpret_cast<__nv_bfloat162*>(p)[0] = hp0;
        reinterpret_cast<__nv_bfloat162*>(p)[1] = hp1;
        reinterpret_cast<__nv_bfloat162*>(p + DINc)[0] = lp0;
        reinterpret_cast<__nv_bfloat162*>(p + DINc)[1] = lp1;
        reinterpret_cast<__nv_bfloat162*>(p + 2 * DINc)[0] = hp0;
        reinterpret_cast<__nv_bfloat162*>(p + 2 * DINc)[1] = hp1;
        return;
    }
    if (bid < Nn + 256 + 3072 + 64) {
        const float* W; __nv_bfloat16* P; int K, N, nb, kb;
        int id = bid - Nn;
        if (id < 256) {
            W = W_in; P = Bpk + OFF_WIN; K = DINc; N = DHc;
            nb = id & 7; kb = id >> 3;
        } else if (id < 256 + 3072) {
            int id2 = id - 256;
            int mat = id2 >> 9;
            int t = id2 & 511;
            int l = mat >> 1, side = mat & 1;
            W = (side == 0 ? Wl : Wr) + (size_t)l * DHc * HDc;
            P = Bpk + OFF_WLR(l) + (size_t)side * HDc * 3 * DHc;
            K = DHc; N = HDc;
            nb = t & 63; kb = t >> 6;
        } else {
            int id2 = id - 256 - 3072;
            W = W_out; P = Bpk + OFF_WOUT; K = DHc; N = DHc;
            nb = id2 & 7; kb = id2 >> 3;
        }
        __shared__ float tbuf[32][33];
        int tx = tid & 31, ty = tid >> 5;
        #pragma unroll
        for (int i = 0; i < 32; i += 8)
            tbuf[ty + i][tx] = W[(size_t)(kb * 32 + ty + i) * N + nb * 32 + tx];
        __syncthreads();
        int K3 = 3 * K;
        #pragma unroll
        for (int i = 0; i < 32; i += 8) {
            int n = nb * 32 + ty + i;
            int k = kb * 32 + tx;
            float v = tbuf[tx][ty + i];
            __nv_bfloat16 hi = __float2bfloat16(v);
            __nv_bfloat16 lo = __float2bfloat16(v - __bfloat162float(hi));
            P[(size_t)n * K3 + k]         = hi;
            P[(size_t)n * K3 + K + k]     = hi;
            P[(size_t)n * K3 + 2 * K + k] = lo;
        }
        return;
    }
    {
        int id = bid - (Nn + 256 + 3072 + 64);
        int lt = id >> 3;
        int jb = id & 7;
        int l = lt / NTc, t = lt % NTc;
        int j = jb * 256 + tid;
        const float* w = We + (size_t)l * DHc * HDc + j;
        const float* e = edge_emb + t * DHc;
        float s = 0.f;
        #pragma unroll 4
        for (int k = 0; k < DHc; ++k) s = fmaf(e[k], w[(size_t)k * HDc], s);
        g_table[(size_t)l * NTc * HDc + t * HDc + j] = s;
    }
}

// ---------------- GEMM kernel 1 (proj): CTA 128x128, warp 32x64, 3-stage, 2 CTA/SM ----
#define GSTAGE 3
#define STG_BYTES 32768
#define GEMM_SMEM (GSTAGE * STG_BYTES)

__global__ void __launch_bounds__(256, 2)
k_gemm_mma(const __nv_bfloat16* __restrict__ A, const __nv_bfloat16* __restrict__ B,
           const float* __restrict__ bias, float* __restrict__ C, int Ktot, int Nc,
           const float* __restrict__ emb, const int* __restrict__ types,
           __nv_bfloat16* __restrict__ packA) {
    extern __shared__ __align__(1024) char smem[];
    const uint32_t sb = smem_u32(smem);
    const int tid = threadIdx.x;
    const int lane = tid & 31, w = tid >> 5;
    const int wm = w & 3, wn = w >> 2;
    const int row0 = blockIdx.y * 128;
    const int col0 = blockIdx.x * 128;
    const int nch = Ktot >> 6;

    float acc[2][8][4];
    #pragma unroll
    for (int i = 0; i < 2; ++i)
        #pragma unroll
        for (int j = 0; j < 8; ++j)
            #pragma unroll
            for (int q = 0; q < 4; ++q) acc[i][j][q] = 0.f;

    uint32_t sm_off[4];
    const __nv_bfloat16* gA[4];
    const __nv_bfloat16* gB[4];
    #pragma unroll
    for (int u = 0; u < 4; ++u) {
        int i = tid + u * 256;
        int r = i >> 3, seg = i & 7;
        uint32_t off = (uint32_t)(r * 128 + seg * 16);
        sm_off[u] = off ^ ((off >> 3) & 0x70);
        gA[u] = A + (size_t)(row0 + r) * Ktot + (seg << 3);
        gB[u] = B + (size_t)(col0 + r) * Ktot + (seg << 3);
    }
    auto load_chunk = [&](int c) {
        const uint32_t s = sb + (uint32_t)((c % GSTAGE) * STG_BYTES);
        const int kof = c << 6;
        #pragma unroll
        for (int u = 0; u < 4; ++u) cp16(s + sm_off[u], gA[u] + kof);
        #pragma unroll
        for (int u = 0; u < 4; ++u) cp16(s + 16384 + sm_off[u], gB[u] + kof);
        asm volatile("cp.async.commit_group;");
    };
    #pragma unroll
    for (int c = 0; c < GSTAGE - 1; ++c) load_chunk(c);

    uint32_t a_base[2], a_swz[2];
    #pragma unroll
    for (int mb = 0; mb < 2; ++mb) {
        int row = wm * 32 + mb * 16 + (lane & 15);
        a_base[mb] = (uint32_t)(row * 128 + ((lane >> 4) << 4));
        a_swz[mb] = (uint32_t)((row & 7) << 4);
    }
    uint32_t b_base[4], b_swz[4];
    #pragma unroll
    for (int nb = 0; nb < 4; ++nb) {
        int row = wn * 64 + nb * 16 + (lane & 7) + ((lane >> 4) << 3);
        b_base[nb] = (uint32_t)(row * 128 + (((lane >> 3) & 1) << 4));
        b_swz[nb] = (uint32_t)((row & 7) << 4);
    }

    for (int c = 0; c < nch; ++c) {
        asm volatile("cp.async.wait_group %0;" :: "n"(GSTAGE - 2));
        __syncthreads();
        if (c + GSTAGE - 1 < nch) load_chunk(c + GSTAGE - 1);
        else asm volatile("cp.async.commit_group;");
        const uint32_t stb = sb + (uint32_t)((c % GSTAGE) * STG_BYTES);
        #pragma unroll
        for (int kk = 0; kk < 4; ++kk) {
            const uint32_t kby = (uint32_t)(kk * 32);
            uint32_t a[2][4];
            #pragma unroll
            for (int mb = 0; mb < 2; ++mb)
                ldsm_x4(a[mb], stb + ((a_base[mb] + kby) ^ a_swz[mb]));
            uint32_t b[4][4];
            #pragma unroll
            for (int nb = 0; nb < 4; ++nb)
                ldsm_x4(b[nb], stb + 16384 + ((b_base[nb] + kby) ^ b_swz[nb]));
            #pragma unroll
            for (int mb = 0; mb < 2; ++mb)
                #pragma unroll
                for (int nb = 0; nb < 4; ++nb) {
                    mma_bf16(acc[mb][2 * nb],     a[mb], b[nb][0], b[nb][1]);
                    mma_bf16(acc[mb][2 * nb + 1], a[mb], b[nb][2], b[nb][3]);
                }
        }
    }

    const int r_base = row0 + wm * 32 + (lane >> 2);
    const int c_base = col0 + wn * 64 + ((lane & 3) << 1);
    const int K3 = 3 * Nc;
    #pragma unroll
    for (int mb = 0; mb < 2; ++mb) {
        const int r1 = r_base + mb * 16;
        const int r2 = r1 + 8;
        #pragma unroll
        for (int nt = 0; nt < 8; ++nt) {
            const int col = c_base + nt * 8;
            float bx = bias[col], by = bias[col + 1];
            float e1x = 0.f, e1y = 0.f, e2x = 0.f, e2y = 0.f;
            if (emb) {
                const float* em1 = emb + (size_t)types[r1] * Nc + col;
                const float* em2 = emb + (size_t)types[r2] * Nc + col;
                e1x = em1[0]; e1y = em1[1]; e2x = em2[0]; e2y = em2[1];
            }
            float v00 = acc[mb][nt][0] + bx + e1x;
            float v01 = acc[mb][nt][1] + by + e1y;
            float v10 = acc[mb][nt][2] + bx + e2x;
            float v11 = acc[mb][nt][3] + by + e2y;
            if (C) {
                float2 t0 = {v00, v01}, t1 = {v10, v11};
                *reinterpret_cast<float2*>(&C[(size_t)r1 * Nc + col]) = t0;
                *reinterpret_cast<float2*>(&C[(size_t)r2 * Nc + col]) = t1;
            }
            if (packA) {
                __nv_bfloat16 h00 = __float2bfloat16(v00);
                __nv_bfloat16 h01 = __float2bfloat16(v01);
                __nv_bfloat16 h10 = __float2bfloat16(v10);
                __nv_bfloat16 h11 = __float2bfloat16(v11);
                __nv_bfloat162 hp1 = {h00, h01};
                __nv_bfloat162 hp2 = {h10, h11};
                __nv_bfloat162 lp1 = {__float2bfloat16(v00 - __bfloat162float(h00)),
                                      __float2bfloat16(v01 - __bfloat162float(h01))};
                __nv_bfloat162 lp2 = {__float2bfloat16(v10 - __bfloat162float(h10)),
                                      __float2bfloat16(v11 - __bfloat162float(h11))};
                __nv_bfloat16* p1 = packA + (size_t)r1 * K3 + col;
                __nv_bfloat16* p2 = packA + (size_t)r2 * K3 + col;
                *reinterpret_cast<__nv_bfloat162*>(p1)          = hp1;
                *reinterpret_cast<__nv_bfloat162*>(p1 + Nc)     = lp1;
                *reinterpret_cast<__nv_bfloat162*>(p1 + 2 * Nc) = hp1;
                *reinterpret_cast<__nv_bfloat162*>(p2)          = hp2;
                *reinterpret_cast<__nv_bfloat162*>(p2 + Nc)     = lp2;
                *reinterpret_cast<__nv_bfloat162*>(p2 + 2 * Nc) = hp2;
            }
        }
    }
}

// ---------------- GEMM kernel 2 (merged xl|xr): CTA 128x256, warp 64x64, 4-stage ----
#define BGSTAGE 4
#define BSTG_BYTES 49152
#define BGEMM_SMEM (BGSTAGE * BSTG_BYTES)

__global__ void __launch_bounds__(256, 1)
k_gemm_big(const __nv_bfloat16* __restrict__ A, const __nv_bfloat16* __restrict__ B,
           const float* __restrict__ bias, const float* __restrict__ bias2, int halfN,
           __half* __restrict__ C, int Ktot, int Nc) {
    extern __shared__ __align__(1024) char smem[];
    const uint32_t sb = smem_u32(smem);
    const int tid = threadIdx.x;
    const int lane = tid & 31, w = tid >> 5;
    const int wm = w & 1, wn = w >> 1;
    const int row0 = blockIdx.y * 128;
    const int col0 = blockIdx.x * 256;
    const int nch = Ktot >> 6;

    float acc[4][8][4];
    #pragma unroll
    for (int i = 0; i < 4; ++i)
        #pragma unroll
        for (int j = 0; j < 8; ++j)
            #pragma unroll
            for (int q = 0; q < 4; ++q) acc[i][j][q] = 0.f;

    uint32_t sm_offA[4], sm_offB[8];
    const __nv_bfloat16* gA[4];
    const __nv_bfloat16* gB[8];
    #pragma unroll
    for (int u = 0; u < 4; ++u) {
        int i = tid + u * 256;
        int r = i >> 3, seg = i & 7;
        uint32_t off = (uint32_t)(r * 128 + seg * 16);
        sm_offA[u] = off ^ ((off >> 3) & 0x70);
        gA[u] = A + (size_t)(row0 + r) * Ktot + (seg << 3);
    }
    #pragma unroll
    for (int u = 0; u < 8; ++u) {
        int i = tid + u * 256;
        int r = i >> 3, seg = i & 7;
        uint32_t off = (uint32_t)(r * 128 + seg * 16);
        sm_offB[u] = off ^ ((off >> 3) & 0x70);
        gB[u] = B + (size_t)(col0 + r) * Ktot + (seg << 3);
    }
    auto load_chunk = [&](int c) {
        const uint32_t s = sb + (uint32_t)((c % BGSTAGE) * BSTG_BYTES);
        const int kof = c << 6;
        #pragma unroll
        for (int u = 0; u < 4; ++u) cp16(s + sm_offA[u], gA[u] + kof);
        #pragma unroll
        for (int u = 0; u < 8; ++u) cp16(s + 16384 + sm_offB[u], gB[u] + kof);
        asm volatile("cp.async.commit_group;");
    };
    #pragma unroll
    for (int c = 0; c < BGSTAGE - 1; ++c) load_chunk(c);

    uint32_t a_base[4], a_swz[4];
    #pragma unroll
    for (int mb = 0; mb < 4; ++mb) {
        int row = wm * 64 + mb * 16 + (lane & 15);
        a_base[mb] = (uint32_t)(row * 128 + ((lane >> 4) << 4));
        a_swz[mb] = (uint32_t)((row & 7) << 4);
    }
    uint32_t b_base[4], b_swz[4];
    #pragma unroll
    for (int nb = 0; nb < 4; ++nb) {
        int row = wn * 64 + nb * 16 + (lane & 7) + ((lane >> 4) << 3);
        b_base[nb] = (uint32_t)(row * 128 + (((lane >> 3) & 1) << 4));
        b_swz[nb] = (uint32_t)((row & 7) << 4);
    }

    for (int c = 0; c < nch; ++c) {
        asm volatile("cp.async.wait_group %0;" :: "n"(BGSTAGE - 2));
        __syncthreads();
        if (c + BGSTAGE - 1 < nch) load_chunk(c + BGSTAGE - 1);
        else asm volatile("cp.async.commit_group;");
        const uint32_t stb = sb + (uint32_t)((c % BGSTAGE) * BSTG_BYTES);
        #pragma unroll
        for (int kk = 0; kk < 4; ++kk) {
            const uint32_t kby = (uint32_t)(kk * 32);
            uint32_t a[4][4];
            #pragma unroll
            for (int mb = 0; mb < 4; ++mb)
                ldsm_x4(a[mb], stb + ((a_base[mb] + kby) ^ a_swz[mb]));
            uint32_t b[4][4];
            #pragma unroll
            for (int nb = 0; nb < 4; ++nb)
                ldsm_x4(b[nb], stb + 16384 + ((b_base[nb] + kby) ^ b_swz[nb]));
            #pragma unroll
            for (int mb = 0; mb < 4; ++mb)
                #pragma unroll
                for (int nb = 0; nb < 4; ++nb) {
                    mma_bf16(acc[mb][2 * nb],     a[mb], b[nb][0], b[nb][1]);
                    mma_bf16(acc[mb][2 * nb + 1], a[mb], b[nb][2], b[nb][3]);
                }
        }
    }

    const float* bp = bias;
    int cadj = 0;
    if (bias2 && col0 >= halfN) { bp = bias2; cadj = halfN; }
    const int r_base = row0 + wm * 64 + (lane >> 2);
    const int c_base = col0 + wn * 64 + ((lane & 3) << 1);
    #pragma unroll
    for (int mb = 0; mb < 4; ++mb) {
        const int r1 = r_base + mb * 16;
        const int r2 = r1 + 8;
        #pragma unroll
        for (int nt = 0; nt < 8; ++nt) {
            const int col = c_base + nt * 8;
            float bx = bp[col - cadj], by = bp[col + 1 - cadj];
            __half2 t0 = __floats2half2_rn(acc[mb][nt][0] + bx, acc[mb][nt][1] + by);
            __half2 t1 = __floats2half2_rn(acc[mb][nt][2] + bx, acc[mb][nt][3] + by);
            *reinterpret_cast<__half2*>(&C[(size_t)r1 * Nc + col]) = t0;
            *reinterpret_cast<__half2*>(&C[(size_t)r2 * Nc + col]) = t1;
        }
    }
}

// ---------------- fused GATv2 edge kernel (fp16 xlr, pipelined) ----------------
__global__ void __launch_bounds__(256)
k_edge(const int* __restrict__ edge_index, const int* __restrict__ edge_attr,
       const float* __restrict__ att_l, const float* __restrict__ bgat_l,
       int loff, __nv_bfloat16* __restrict__ packH) {
    const int n = blockIdx.x;
    const int tid = threadIdx.x;
    const int lane = tid & 31;
    const int base = ((tid >> 5) << 8) + (lane << 3);

    __shared__ float s_xr[HDc];
    __shared__ float s_att[HDc];
    __shared__ float s_lee[HDc];
    __shared__ float s_out[HDc];

    const int r0 = g_rowptr[n], r1 = g_rowptr[n + 1];
    const int deg = r1 - r0;
    const float inv = 1.0f / (float)(deg > 1 ? deg : 1);

    float c0 = (float)g_hist[n * NTc + 0];
    float c1 = (float)g_hist[n * NTc + 1];
    float c2 = (float)g_hist[n * NTc + 2];
    float c3 = (float)g_hist[n * NTc + 3];
    float c4 = (float)g_hist[n * NTc + 4];

    const float* tb = g_table + loff;
    // load xr (fp16, 16B per thread)
    {
        int j8 = tid * 8;
        uint4 raw = *reinterpret_cast<const uint4*>(g_xlr + (size_t)n * N2c + HDc + j8);
        __half2 p0 = *reinterpret_cast<__half2*>(&raw.x);
        __half2 p1 = *reinterpret_cast<__half2*>(&raw.y);
        __half2 p2 = *reinterpret_cast<__half2*>(&raw.z);
        __half2 p3 = *reinterpret_cast<__half2*>(&raw.w);
        s_xr[j8 + 0] = __half2float(p0.x); s_xr[j8 + 1] = __half2float(p0.y);
        s_xr[j8 + 2] = __half2float(p1.x); s_xr[j8 + 3] = __half2float(p1.y);
        s_xr[j8 + 4] = __half2float(p2.x); s_xr[j8 + 5] = __half2float(p2.y);
        s_xr[j8 + 6] = __half2float(p3.x); s_xr[j8 + 7] = __half2float(p3.y);
    }
    #pragma unroll
    for (int u = 0; u < 8; ++u) {
        int j = tid + u * 256;
        s_att[j] = att_l[j];
        float v = c0 * tb[0 * HDc + j];
        v = fmaf(c1, tb[1 * HDc + j], v);
        v = fmaf(c2, tb[2 * HDc + j], v);
        v = fmaf(c3, tb[3 * HDc + j], v);
        v = fmaf(c4, tb[4 * HDc + j], v);
        s_lee[j] = v * inv;
    }
    __syncthreads();

    float m = -1e30f, d = 0.f;
    float acc[8];
    #pragma unroll
    for (int i = 0; i < 8; ++i) acc[i] = 0.f;

    // prefetch first edge's (src, type)
    int s_cur = n, t_cur = -1;
    if (r0 < r1) {
        int e = g_eid[r0];
        s_cur = edge_index[e];
        t_cur = edge_attr[e];
    }
    for (int idx = r0; idx <= r1; ++idx) {
        const bool isloop = (idx == r1);
        // issue xlv load for current edge (16B)
        uint4 raw = *reinterpret_cast<const uint4*>(g_xlr + (size_t)s_cur * N2c + base);
        // prefetch next edge's indices (overlaps with compute below)
        int s_nxt = n, t_nxt = -1;
        if (idx + 1 < r1) {
            int e = g_eid[idx + 1];
            s_nxt = edge_index[e];
            t_nxt = edge_attr[e];
        }
        __half2 p0 = *reinterpret_cast<__half2*>(&raw.x);
        __half2 p1 = *reinterpret_cast<__half2*>(&raw.y);
        __half2 p2 = *reinterpret_cast<__half2*>(&raw.z);
        __half2 p3 = *reinterpret_cast<__half2*>(&raw.w);
        float xlv[8];
        xlv[0] = __half2float(p0.x); xlv[1] = __half2float(p0.y);
        xlv[2] = __half2float(p1.x); xlv[3] = __half2float(p1.y);
        xlv[4] = __half2float(p2.x); xlv[5] = __half2float(p2.y);
        xlv[6] = __half2float(p3.x); xlv[7] = __half2float(p3.y);

        const float* tab = isloop ? (s_lee + base) : (tb + (size_t)t_cur * HDc + base);
        float part = 0.f;
        #pragma unroll
        for (int i = 0; i < 8; ++i) {
            float z = xlv[i] + s_xr[base + i] + tab[i];
            z = z > 0.f ? z : 0.2f * z;
            part = fmaf(z, s_att[base + i], part);
        }
        #pragma unroll
        for (int o = 16; o > 0; o >>= 1)
            part += __shfl_xor_sync(0xffffffffu, part, o);

        float mn = fmaxf(m, part);
        float sc = __expf(m - mn);
        float p  = __expf(part - mn);
        d = d * sc + p;
        #pragma unroll
        for (int i = 0; i < 8; ++i) acc[i] = fmaf(acc[i], sc, p * xlv[i]);
        m = mn;
        s_cur = s_nxt; t_cur = t_nxt;
    }

    float invd = 1.0f / d;
    #pragma unroll
    for (int i = 0; i < 8; ++i) s_out[base + i] = acc[i] * invd;
    __syncthreads();

    {
        int c = tid;
        float v = 0.f;
        #pragma unroll
        for (int h = 0; h < HHc; ++h) v += s_out[h * DHc + c];
        v = fmaf(v, 0.125f, bgat_l[c]);
        v = fmaxf(v, 0.f);
        __nv_bfloat16 hi = __float2bfloat16(v);
        __nv_bfloat16 lo = __float2bfloat16(v - __bfloat162float(hi));
        __nv_bfloat16* p = packH + (size_t)n * (3 * DHc) + c;
        p[0]        = hi;
        p[DHc]      = lo;
        p[2 * DHc]  = hi;
    }
}

// ---------------- host orchestration ----------------
extern "C" void kernel_launch(void* const* d_in, const int* in_sizes, int n_in,
                              void* d_out, int out_size) {
    const float* x         = (const float*)d_in[0];
    const int*   edge_index= (const int*)  d_in[1];
    const int*   edge_attr = (const int*)  d_in[2];
    const int*   node_types= (const int*)  d_in[3];
    const float* W_in      = (const float*)d_in[4];
    const float* b_in      = (const float*)d_in[5];
    const float* node_emb  = (const float*)d_in[6];
    const float* edge_emb  = (const float*)d_in[7];
    const float* Wl        = (const float*)d_in[8];
    const float* bl        = (const float*)d_in[9];
    const float* Wr        = (const float*)d_in[10];
    const float* br        = (const float*)d_in[11];
    const float* We        = (const float*)d_in[12];
    const float* att       = (const float*)d_in[13];
    const float* b_gat     = (const float*)d_in[14];
    const float* W_out     = (const float*)d_in[15];
    const float* b_out     = (const float*)d_in[16];
    float* out = (float*)d_out;

    __half* xlr;    cudaGetSymbolAddress((void**)&xlr, g_xlr);
    __nv_bfloat16* Apk; cudaGetSymbolAddress((void**)&Apk, g_Apack);
    __nv_bfloat16* Hpk; cudaGetSymbolAddress((void**)&Hpk, g_hpack);
    __nv_bfloat16* Bpk; cudaGetSymbolAddress((void**)&Bpk, g_Bpack);

    cudaFuncSetAttribute(k_gemm_mma, cudaFuncAttributeMaxDynamicSharedMemorySize, GEMM_SMEM);
    cudaFuncSetAttribute(k_gemm_big, cudaFuncAttributeMaxDynamicSharedMemorySize, BGEMM_SMEM);

    // 1: pack everything
    k_pack_all<<<Nn + 256 + 3072 + 64 + 120, 256>>>(x, W_in, Wl, Wr, W_out,
                                                    edge_emb, We, Apk, Bpk);
    // 2: CSR zero
    k_zero<<<(Nn * NTc + 255) / 256, 256>>>();
    // 3: input projection -> packed h0
    k_gemm_mma<<<dim3(2, 64), 256, GEMM_SMEM>>>(
        Apk, Bpk + OFF_WIN, b_in, nullptr, 3 * DINc, DHc, node_emb, node_types, Hpk);
    // 4: merged xl|xr GEMM layer 0   <- ncu capture slot
    k_gemm_big<<<dim3(N2c / 256, 64), 256, BGEMM_SMEM>>>(
        Hpk, Bpk + OFF_WLR(0), bl, br, HDc, xlr, 3 * DHc, N2c);
    // 5-8: finish CSR
    k_count<<<(Ee + 255) / 256, 256>>>(edge_index, edge_attr);
    k_scan<<<1, 256>>>();
    k_fill<<<(Ee + 255) / 256, 256>>>(edge_index);
    k_sort<<<(Nn + 255) / 256, 256>>>();

    for (int l = 0; l < LLc; ++l) {
        if (l > 0) {
            k_gemm_big<<<dim3(N2c / 256, 64), 256, BGEMM_SMEM>>>(
                Hpk, Bpk + OFF_WLR(l), bl + (size_t)l * HDc, br + (size_t)l * HDc,
                HDc, xlr, 3 * DHc, N2c);
        }
        k_edge<<<Nn, 256>>>(edge_index, edge_attr,
                            att + (size_t)l * HHc * DHc,
                            b_gat + (size_t)l * DHc, l * NTc * HDc, Hpk);
    }

    // output projection -> d_out fp32
    k_gemm_mma<<<dim3(2, 64), 256, GEMM_SMEM>>>(
        Hpk, Bpk + OFF_WOUT, b_out, out, 3 * DHc, DHc, nullptr, nullptr, nullptr);

    (void)in_sizes; (void)n_in; (void)out_size;
}